// round 14
// baseline (speedup 1.0000x reference)
#include <cuda_runtime.h>
#include <cuda_bf16.h>
#include <mma.h>
#include <cstdint>
#include <math.h>

using namespace nvcuda;

#define B_    2
#define S_    2048
#define D_    1024
#define H_    16
#define QKV_  192
#define NQKV  (H_ * QKV_)   /* 3072 */
#define MROWS (B_ * S_)     /* 4096 */

// ---------------- scratch ---------------------------------------------------
__device__ __nv_bfloat16 g_qkvhi[(size_t)MROWS * NQKV];
__device__ __nv_bfloat16 g_qkvlo[(size_t)MROWS * NQKV];
__device__ __nv_bfloat16 g_xhi[(size_t)MROWS * D_];
__device__ __nv_bfloat16 g_xlo[(size_t)MROWS * D_];
__device__ __nv_bfloat16 g_wehi[(size_t)NQKV * D_];   // [N][K]
__device__ __nv_bfloat16 g_welo[(size_t)NQKV * D_];
__device__ __nv_bfloat16 g_wohi[(size_t)D_ * D_];
__device__ __nv_bfloat16 g_wolo[(size_t)D_ * D_];
__device__ __nv_bfloat16 g_ahi[(size_t)MROWS * D_];
__device__ __nv_bfloat16 g_alo[(size_t)MROWS * D_];
__device__ float g_y[(size_t)MROWS * D_];
__device__ float g_sufv[(size_t)B_ * H_ * 33 * 64];

// ---------------- helpers ---------------------------------------------------
__device__ __forceinline__ uint32_t smem_u32(const void* p) {
    uint32_t a;
    asm("{ .reg .u64 t; cvta.to.shared.u64 t, %1; cvt.u32.u64 %0, t; }" : "=r"(a) : "l"(p));
    return a;
}
#define CP_ASYNC16(dst, src) \
    asm volatile("cp.async.cg.shared.global [%0], [%1], 16;" :: "r"(dst), "l"(src))
#define CP_COMMIT() asm volatile("cp.async.commit_group;")
#define CP_WAIT0()  asm volatile("cp.async.wait_group 0;")

// ---------------------------------------------------------------------------
// HMMA GEMM: 128x128 tile, 512 thr (16 warps, 32x32 each), BK=32, 2 CTAs/SM.
// ---------------------------------------------------------------------------
#define BM 128
#define BN 128
#define BK 32
#define GP 40
#define MATB (BM * GP * 2)
#define STAGEB (4 * MATB)
#define GSMEM (2 * STAGEB)

template<int MODE>
__global__ void __launch_bounds__(512, 2) gemm_wmma(
    const __nv_bfloat16* __restrict__ Ahi, const __nv_bfloat16* __restrict__ Alo,
    const __nv_bfloat16* __restrict__ Bhi, const __nv_bfloat16* __restrict__ Blo,
    float* __restrict__ C, __nv_bfloat16* __restrict__ Chi,
    __nv_bfloat16* __restrict__ Clo, int M, int N, int K)
{
    extern __shared__ __align__(16) char smem[];
    const uint32_t sb = smem_u32(smem);
    const int tid = threadIdx.x;
    const int wid = tid >> 5;
    const int wm = wid & 3, wn = wid >> 2;     // 4x4 warp grid, 32x32 each
    const int m0 = blockIdx.y * BM, n0 = blockIdx.x * BN;

    wmma::fragment<wmma::accumulator, 16, 16, 16, float> acc[2][2];
#pragma unroll
    for (int i = 0; i < 2; i++)
#pragma unroll
        for (int j = 0; j < 2; j++) wmma::fill_fragment(acc[i][j], 0.0f);

    // loader: one uint4 per matrix per thread (512 uint4 = 128x32 bf16 tile)
    const int lrow = tid >> 2;
    const int lcb = (tid & 3) * 16;
    const char* gAh = (const char*)&Ahi[(size_t)(m0 + lrow) * K] + lcb;
    const char* gAl = (const char*)&Alo[(size_t)(m0 + lrow) * K] + lcb;
    const char* gBh = (const char*)&Bhi[(size_t)(n0 + lrow) * K] + lcb;
    const char* gBl = (const char*)&Blo[(size_t)(n0 + lrow) * K] + lcb;
    const uint32_t soff = lrow * (GP * 2) + lcb;

    const int KT = K / BK;
    auto issue = [&](int st, int kt) {
        const uint32_t base = sb + st * STAGEB + soff;
        const size_t gk = (size_t)kt * (BK * 2);
        CP_ASYNC16(base,          gAh + gk);
        CP_ASYNC16(base + MATB,   gAl + gk);
        CP_ASYNC16(base + 2*MATB, gBh + gk);
        CP_ASYNC16(base + 3*MATB, gBl + gk);
    };

    issue(0, 0);
    CP_COMMIT();

    for (int kt = 0; kt < KT; kt++) {
        const int st = kt & 1;
        CP_WAIT0();
        __syncthreads();
        if (kt + 1 < KT) { issue(st ^ 1, kt + 1); CP_COMMIT(); }

        const __nv_bfloat16* sAh = (const __nv_bfloat16*)(smem + st * STAGEB);
        const __nv_bfloat16* sAl = sAh + BM * GP;
        const __nv_bfloat16* sBh = sAl + BM * GP;
        const __nv_bfloat16* sBl = sBh + BM * GP;

#pragma unroll
        for (int kk = 0; kk < BK; kk += 16) {
            wmma::fragment<wmma::matrix_b, 16, 16, 16, __nv_bfloat16, wmma::col_major> bh[2], bl[2];
#pragma unroll
            for (int j = 0; j < 2; j++) {
                wmma::load_matrix_sync(bh[j], sBh + (wn * 32 + j * 16) * GP + kk, GP);
                wmma::load_matrix_sync(bl[j], sBl + (wn * 32 + j * 16) * GP + kk, GP);
            }
#pragma unroll
            for (int i = 0; i < 2; i++) {
                wmma::fragment<wmma::matrix_a, 16, 16, 16, __nv_bfloat16, wmma::row_major> ah, al;
                wmma::load_matrix_sync(ah, sAh + (wm * 32 + i * 16) * GP + kk, GP);
                wmma::load_matrix_sync(al, sAl + (wm * 32 + i * 16) * GP + kk, GP);
#pragma unroll
                for (int j = 0; j < 2; j++) wmma::mma_sync(acc[i][j], ah, bh[j], acc[i][j]);
#pragma unroll
                for (int j = 0; j < 2; j++) wmma::mma_sync(acc[i][j], ah, bl[j], acc[i][j]);
#pragma unroll
                for (int j = 0; j < 2; j++) wmma::mma_sync(acc[i][j], al, bh[j], acc[i][j]);
            }
        }
    }

    if (MODE == 0) {
#pragma unroll
        for (int i = 0; i < 2; i++)
#pragma unroll
            for (int j = 0; j < 2; j++)
                wmma::store_matrix_sync(
                    &C[(size_t)(m0 + wm * 32 + i * 16) * N + n0 + wn * 32 + j * 16],
                    acc[i][j], N, wmma::mem_row_major);
    } else {
        __syncthreads();
        float* stage = (float*)smem;
#pragma unroll
        for (int i = 0; i < 2; i++)
#pragma unroll
            for (int j = 0; j < 2; j++)
                wmma::store_matrix_sync(
                    &stage[(size_t)(wm * 32 + i * 16) * BN + wn * 32 + j * 16],
                    acc[i][j], BN, wmma::mem_row_major);
        __syncthreads();
#pragma unroll
        for (int it = 0; it < 8; it++) {
            const int fi = tid + it * 512;       // 4096 float4 total
            const int row = fi >> 5, c4 = (fi & 31) * 4;
            float4 v = *(const float4*)&stage[row * BN + c4];
            __nv_bfloat16 h0 = __float2bfloat16(v.x), h1 = __float2bfloat16(v.y);
            __nv_bfloat16 h2 = __float2bfloat16(v.z), h3 = __float2bfloat16(v.w);
            __nv_bfloat162 hA(h0, h1), hB(h2, h3);
            __nv_bfloat162 lA(__float2bfloat16(v.x - __bfloat162float(h0)),
                              __float2bfloat16(v.y - __bfloat162float(h1)));
            __nv_bfloat162 lB(__float2bfloat16(v.z - __bfloat162float(h2)),
                              __float2bfloat16(v.w - __bfloat162float(h3)));
            const size_t o = (size_t)(m0 + row) * N + n0 + c4;
            *(__nv_bfloat162*)&Chi[o] = hA; *(__nv_bfloat162*)&Chi[o + 2] = hB;
            *(__nv_bfloat162*)&Clo[o] = lA; *(__nv_bfloat162*)&Clo[o + 2] = lB;
        }
    }
}

// ---------------------------------------------------------------------------
__global__ void __launch_bounds__(256) split4(const float4* __restrict__ in,
                                              __nv_bfloat162* __restrict__ hi,
                                              __nv_bfloat162* __restrict__ lo,
                                              int n4) {
    int i = blockIdx.x * 256 + threadIdx.x;
    if (i >= n4) return;
    float4 v = in[i];
    __nv_bfloat16 h0 = __float2bfloat16(v.x), h1 = __float2bfloat16(v.y);
    __nv_bfloat16 h2 = __float2bfloat16(v.z), h3 = __float2bfloat16(v.w);
    hi[i * 2 + 0] = __nv_bfloat162(h0, h1);
    hi[i * 2 + 1] = __nv_bfloat162(h2, h3);
    lo[i * 2 + 0] = __nv_bfloat162(__float2bfloat16(v.x - __bfloat162float(h0)),
                                   __float2bfloat16(v.y - __bfloat162float(h1)));
    lo[i * 2 + 1] = __nv_bfloat162(__float2bfloat16(v.z - __bfloat162float(h2)),
                                   __float2bfloat16(v.w - __bfloat162float(h3)));
}

__global__ void __launch_bounds__(256) transpose_split(const float* __restrict__ W,
                                                       __nv_bfloat16* __restrict__ hi,
                                                       __nv_bfloat16* __restrict__ lo,
                                                       int K, int N) {
    __shared__ float t[32][33];
    const int n0 = blockIdx.x * 32, k0 = blockIdx.y * 32;
    const int x = threadIdx.x, y = threadIdx.y;
#pragma unroll
    for (int i = 0; i < 32; i += 8)
        t[y + i][x] = W[(size_t)(k0 + y + i) * N + n0 + x];
    __syncthreads();
#pragma unroll
    for (int i = 0; i < 32; i += 8) {
        float v = t[x][y + i];
        __nv_bfloat16 h = __float2bfloat16(v);
        size_t o = (size_t)(n0 + y + i) * K + k0 + x;
        hi[o] = h;
        lo[o] = __float2bfloat16(v - __bfloat162float(h));
    }
}

// ---------------------------------------------------------------------------
__global__ void __launch_bounds__(64) sufv_partial(const __nv_bfloat16* __restrict__ qhi,
                                                   const __nv_bfloat16* __restrict__ qlo,
                                                   float* __restrict__ sufv) {
    const int t = blockIdx.x, h = blockIdx.y, b = blockIdx.z, d = threadIdx.x;
    const size_t col = (size_t)h * QKV_ + 128 + d;
    float acc = 0.0f;
#pragma unroll 8
    for (int kk = 0; kk < 64; kk++) {
        const size_t o = (size_t)(b * S_ + t * 64 + kk) * NQKV + col;
        acc += __bfloat162float(qhi[o]) + __bfloat162float(qlo[o]);
    }
    sufv[((size_t)(b * H_ + h) * 33 + t) * 64 + d] = acc;
}

__global__ void __launch_bounds__(64) sufv_scan(float* __restrict__ sufv) {
    const int h = blockIdx.x, b = blockIdx.y, d = threadIdx.x;
    float* base = &sufv[((size_t)(b * H_ + h) * 33) * 64 + d];
    float acc = 0.0f;
    base[32 * 64] = 0.0f;
    for (int t = 31; t >= 0; t--) {
        acc += base[t * 64];
        base[t * 64] = acc;
    }
}

// ---------------------------------------------------------------------------
// wmma flash attention (R11/R12 proven version, unchanged).
// ---------------------------------------------------------------------------
#define AP 72
#define SFP 68
#define AQH 0
#define AQL (AQH + 64 * AP * 2)
#define AKV (AQL + 64 * AP * 2)
#define KVMAT (64 * AP * 2)
#define KVSTAGE (4 * KVMAT)
#define ASF (AKV + 2 * KVSTAGE)
#define ASMEM (ASF + 64 * SFP * 4)

__global__ void __launch_bounds__(256, 2) attn_wmma(
    const __nv_bfloat16* __restrict__ qkvhi, const __nv_bfloat16* __restrict__ qkvlo,
    const float* __restrict__ sufv,
    __nv_bfloat16* __restrict__ ahi, __nv_bfloat16* __restrict__ alo)
{
    extern __shared__ __align__(32) char smem[];
    const uint32_t sb = smem_u32(smem);
    __nv_bfloat16* sQh = (__nv_bfloat16*)(smem + AQH);
    __nv_bfloat16* sQl = (__nv_bfloat16*)(smem + AQL);
    float* sSF = (float*)(smem + ASF);

    const int tid = threadIdx.x, wid = tid >> 5;
    const int pr  = wid & 3;
    const int sub = wid >> 2;
    const int wrow = pr * 16;
    const int wcol = sub * 2;
    const int qt = gridDim.x - 1 - blockIdx.x;
    const int h = blockIdx.y, b = blockIdx.z;
    const int q0 = qt * 64;
    const size_t base = (size_t)b * S_ * NQKV + (size_t)h * QKV_;

    auto issue_kv = [&](int st, int kt) {
#pragma unroll
        for (int jj = 0; jj < 2; jj++) {
            const int row = (tid >> 3) + jj * 32;
            const int c8 = (tid & 7) * 8;
            const uint32_t stb = sb + AKV + st * KVSTAGE + (uint32_t)(row * AP + c8) * 2;
            const char* gh = (const char*)(qkvhi + base + (size_t)(kt * 64 + row) * NQKV + c8);
            const char* gl = (const char*)(qkvlo + base + (size_t)(kt * 64 + row) * NQKV + c8);
            CP_ASYNC16(stb,             gh + 128);
            CP_ASYNC16(stb + KVMAT,     gl + 128);
            CP_ASYNC16(stb + 2*KVMAT,   gh + 256);
            CP_ASYNC16(stb + 3*KVMAT,   gl + 256);
        }
    };

#pragma unroll
    for (int j = 0; j < 2; j++) {
        const int i = tid + j * 256;
        const int row = i >> 3, c8 = (i & 7) * 8;
        const size_t g = base + (size_t)(q0 + row) * NQKV + c8;
        *(uint4*)&sQh[row * AP + c8] = *(const uint4*)&qkvhi[g];
        *(uint4*)&sQl[row * AP + c8] = *(const uint4*)&qkvlo[g];
    }

    const int srow = tid >> 2;
    const int scb  = (tid & 3) * 16;
    float m = -1e30f, l = 0.0f, alpha = 0.0f;
    float o[16];
#pragma unroll
    for (int c = 0; c < 16; c++) o[c] = 0.0f;
    const float scale = 0.125f;
    const int gq = q0 + srow;

    const int KTILES = qt + 1;
    issue_kv(0, 0);
    CP_COMMIT();

    for (int kt = 0; kt < KTILES; kt++) {
        const int st = kt & 1;
        const int k0 = kt * 64;
        CP_WAIT0();
        __syncthreads();
        if (kt + 1 < KTILES) { issue_kv(st ^ 1, kt + 1); CP_COMMIT(); }

        const __nv_bfloat16* sKh = (const __nv_bfloat16*)(smem + AKV + st * KVSTAGE);
        const __nv_bfloat16* sKl = sKh + 64 * AP;
        const __nv_bfloat16* sVh = sKl + 64 * AP;
        const __nv_bfloat16* sVl = sVh + 64 * AP;
        float* sPV = (float*)(smem + AKV + st * KVSTAGE);

        {
            wmma::fragment<wmma::accumulator, 16, 16, 16, float> sacc[2];
#pragma unroll
            for (int j = 0; j < 2; j++) wmma::fill_fragment(sacc[j], 0.0f);
#pragma unroll
            for (int ks = 0; ks < 4; ks++) {
                const int kk = ks * 16;
                wmma::fragment<wmma::matrix_a, 16, 16, 16, __nv_bfloat16, wmma::row_major> ah, al;
                wmma::load_matrix_sync(ah, sQh + wrow * AP + kk, AP);
                wmma::load_matrix_sync(al, sQl + wrow * AP + kk, AP);
                wmma::fragment<wmma::matrix_b, 16, 16, 16, __nv_bfloat16, wmma::col_major> bh[2], bl[2];
#pragma unroll
                for (int j = 0; j < 2; j++) {
                    wmma::load_matrix_sync(bh[j], sKh + ((wcol + j) * 16) * AP + kk, AP);
                    wmma::load_matrix_sync(bl[j], sKl + ((wcol + j) * 16) * AP + kk, AP);
                }
#pragma unroll
                for (int j = 0; j < 2; j++) wmma::mma_sync(sacc[j], ah, bh[j], sacc[j]);
#pragma unroll
                for (int j = 0; j < 2; j++) wmma::mma_sync(sacc[j], ah, bl[j], sacc[j]);
#pragma unroll
                for (int j = 0; j < 2; j++) wmma::mma_sync(sacc[j], al, bh[j], sacc[j]);
            }
#pragma unroll
            for (int j = 0; j < 2; j++)
                wmma::store_matrix_sync(&sSF[wrow * SFP + (wcol + j) * 16], sacc[j],
                                        SFP, wmma::mem_row_major);
        }
        __syncthreads();

        {
            float s[16];
#pragma unroll
            for (int c4 = 0; c4 < 4; c4++) {
                float4 v = *(const float4*)&sSF[srow * SFP + scb + c4 * 4];
                s[c4 * 4 + 0] = v.x; s[c4 * 4 + 1] = v.y;
                s[c4 * 4 + 2] = v.z; s[c4 * 4 + 3] = v.w;
            }
            const int lim = gq - k0;
#pragma unroll
            for (int c = 0; c < 16; c++) {
                float sv = s[c] * scale;
                if (scb + c > lim) sv = 0.0f;
                s[c] = sv;
            }
            float tmax = s[0];
#pragma unroll
            for (int c = 1; c < 16; c++) tmax = fmaxf(tmax, s[c]);
            tmax = fmaxf(tmax, __shfl_xor_sync(0xffffffffu, tmax, 1));
            tmax = fmaxf(tmax, __shfl_xor_sync(0xffffffffu, tmax, 2));
            const float mn = fmaxf(m, tmax);
            alpha = __expf(m - mn);
            m = mn;
            float ps = 0.0f;
#pragma unroll
            for (int c = 0; c < 16; c++) { s[c] = __expf(s[c] - mn); ps += s[c]; }
            ps += __shfl_xor_sync(0xffffffffu, ps, 1);
            ps += __shfl_xor_sync(0xffffffffu, ps, 2);
            l = l * alpha + ps;
            __nv_bfloat16* sP = (__nv_bfloat16*)sSF;
#pragma unroll
            for (int c4 = 0; c4 < 2; c4++) {
                __nv_bfloat16 hh[8], ll[8];
#pragma unroll
                for (int e = 0; e < 8; e++) {
                    const float p = s[c4 * 8 + e];
                    hh[e] = __float2bfloat16(p);
                    ll[e] = __float2bfloat16(p - __bfloat162float(hh[e]));
                }
                *(uint4*)&sP[srow * 136 + scb + c4 * 8]      = *(const uint4*)hh;
                *(uint4*)&sP[srow * 136 + 64 + scb + c4 * 8] = *(const uint4*)ll;
            }
        }
        __syncthreads();

        {
            const __nv_bfloat16* sPh = (const __nv_bfloat16*)sSF;
            const __nv_bfloat16* sPl = ((const __nv_bfloat16*)sSF) + 64;
            wmma::fragment<wmma::accumulator, 16, 16, 16, float> pacc[2];
#pragma unroll
            for (int j = 0; j < 2; j++) wmma::fill_fragment(pacc[j], 0.0f);
#pragma unroll
            for (int ks = 0; ks < 4; ks++) {
                const int kk = ks * 16;
                wmma::fragment<wmma::matrix_a, 16, 16, 16, __nv_bfloat16, wmma::row_major> ah, al;
                wmma::load_matrix_sync(ah, sPh + wrow * 136 + kk, 136);
                wmma::load_matrix_sync(al, sPl + wrow * 136 + kk, 136);
                wmma::fragment<wmma::matrix_b, 16, 16, 16, __nv_bfloat16, wmma::row_major> bh[2], bl[2];
#pragma unroll
                for (int j = 0; j < 2; j++) {
                    wmma::load_matrix_sync(bh[j], sVh + kk * AP + (wcol + j) * 16, AP);
                    wmma::load_matrix_sync(bl[j], sVl + kk * AP + (wcol + j) * 16, AP);
                }
#pragma unroll
                for (int j = 0; j < 2; j++) wmma::mma_sync(pacc[j], ah, bh[j], pacc[j]);
#pragma unroll
                for (int j = 0; j < 2; j++) wmma::mma_sync(pacc[j], ah, bl[j], pacc[j]);
#pragma unroll
                for (int j = 0; j < 2; j++) wmma::mma_sync(pacc[j], al, bh[j], pacc[j]);
            }
#pragma unroll
            for (int j = 0; j < 2; j++)
                wmma::store_matrix_sync(&sPV[wrow * SFP + (wcol + j) * 16], pacc[j],
                                        SFP, wmma::mem_row_major);
        }
        __syncthreads();

#pragma unroll
        for (int c4 = 0; c4 < 4; c4++) {
            float4 p = *(const float4*)&sPV[srow * SFP + scb + c4 * 4];
            o[c4 * 4 + 0] = o[c4 * 4 + 0] * alpha + p.x;
            o[c4 * 4 + 1] = o[c4 * 4 + 1] * alpha + p.y;
            o[c4 * 4 + 2] = o[c4 * 4 + 2] * alpha + p.z;
            o[c4 * 4 + 3] = o[c4 * 4 + 3] * alpha + p.w;
        }
    }

    const int cnt = S_ - 64 * (qt + 1);
    if (cnt > 0) {
        const float mn = fmaxf(m, 0.0f);
        const float a2 = __expf(m - mn);
        const float e0 = __expf(-mn);
        l = l * a2 + (float)cnt * e0;
        const float* sv = &sufv[((size_t)(b * H_ + h) * 33 + qt + 1) * 64 + scb];
#pragma unroll
        for (int c = 0; c < 16; c++) o[c] = o[c] * a2 + e0 * sv[c];
    }
    const float inv = 1.0f / l;
    const size_t orow = (size_t)(b * S_ + q0 + srow) * D_ + h * 64 + scb;
#pragma unroll
    for (int c4 = 0; c4 < 2; c4++) {
        __nv_bfloat16 hh[8], ll[8];
#pragma unroll
        for (int e = 0; e < 8; e++) {
            const float v = o[c4 * 8 + e] * inv;
            hh[e] = __float2bfloat16(v);
            ll[e] = __float2bfloat16(v - __bfloat162float(hh[e]));
        }
        *(uint4*)&ahi[orow + c4 * 8] = *(const uint4*)hh;
        *(uint4*)&alo[orow + c4 * 8] = *(const uint4*)ll;
    }
}

// ---------------------------------------------------------------------------
__global__ void __launch_bounds__(256) ln_kernel(const float* __restrict__ x,
                                                 const float* __restrict__ y,
                                                 const float* __restrict__ gamma,
                                                 const float* __restrict__ beta,
                                                 float* __restrict__ out) {
    __shared__ float red[8];
    const int row = blockIdx.x, t = threadIdx.x;
    const int lane = t & 31, wid = t >> 5;
    const size_t off = (size_t)row * D_;

    float v[4], s = 0.0f;
#pragma unroll
    for (int i = 0; i < 4; i++) {
        int idx = t + i * 256;
        v[i] = x[off + idx] + y[off + idx];
        s += v[i];
    }
    for (int d = 16; d > 0; d >>= 1) s += __shfl_xor_sync(0xffffffffu, s, d);
    if (lane == 0) red[wid] = s;
    __syncthreads();
    float tot = 0.0f;
#pragma unroll
    for (int w = 0; w < 8; w++) tot += red[w];
    const float mean = tot * (1.0f / D_);
    __syncthreads();
    float ss = 0.0f;
#pragma unroll
    for (int i = 0; i < 4; i++) { float d = v[i] - mean; ss += d * d; }
    for (int d = 16; d > 0; d >>= 1) ss += __shfl_xor_sync(0xffffffffu, ss, d);
    if (lane == 0) red[wid] = ss;
    __syncthreads();
    float tot2 = 0.0f;
#pragma unroll
    for (int w = 0; w < 8; w++) tot2 += red[w];
    const float rstd = rsqrtf(tot2 * (1.0f / D_) + 1e-3f);
#pragma unroll
    for (int i = 0; i < 4; i++) {
        int idx = t + i * 256;
        out[off + idx] = (v[i] - mean) * rstd * gamma[idx] + beta[idx];
    }
}

// ---------------------------------------------------------------------------
extern "C" void kernel_launch(void* const* d_in, const int* in_sizes, int n_in,
                              void* d_out, int out_size) {
    const float* x       = (const float*)d_in[0];
    const float* W_embed = (const float*)d_in[2];
    const float* W_out   = (const float*)d_in[3];
    const float* gamma   = (const float*)d_in[4];
    const float* beta    = (const float*)d_in[5];
    float* out = (float*)d_out;

    __nv_bfloat16 *qhi, *qlo, *xhi, *xlo, *wehi, *welo, *wohi, *wolo, *ahi, *alo;
    float *y, *sufv;
    cudaGetSymbolAddress((void**)&qhi,  g_qkvhi);
    cudaGetSymbolAddress((void**)&qlo,  g_qkvlo);
    cudaGetSymbolAddress((void**)&xhi,  g_xhi);
    cudaGetSymbolAddress((void**)&xlo,  g_xlo);
    cudaGetSymbolAddress((void**)&wehi, g_wehi);
    cudaGetSymbolAddress((void**)&welo, g_welo);
    cudaGetSymbolAddress((void**)&wohi, g_wohi);
    cudaGetSymbolAddress((void**)&wolo, g_wolo);
    cudaGetSymbolAddress((void**)&ahi,  g_ahi);
    cudaGetSymbolAddress((void**)&alo,  g_alo);
    cudaGetSymbolAddress((void**)&y,    g_y);
    cudaGetSymbolAddress((void**)&sufv, g_sufv);

    cudaFuncSetAttribute(gemm_wmma<0>, cudaFuncAttributeMaxDynamicSharedMemorySize, GSMEM);
    cudaFuncSetAttribute(gemm_wmma<1>, cudaFuncAttributeMaxDynamicSharedMemorySize, GSMEM);
    cudaFuncSetAttribute(attn_wmma, cudaFuncAttributeMaxDynamicSharedMemorySize, ASMEM);

    split4<<<(MROWS * D_ / 4 + 255) / 256, 256>>>((const float4*)x,
        (__nv_bfloat162*)xhi, (__nv_bfloat162*)xlo, MROWS * D_ / 4);
    transpose_split<<<dim3(NQKV / 32, D_ / 32), dim3(32, 8)>>>(W_embed, wehi, welo, D_, NQKV);
    transpose_split<<<dim3(D_ / 32, D_ / 32), dim3(32, 8)>>>(W_out, wohi, wolo, D_, D_);

    gemm_wmma<1><<<dim3(NQKV / BN, MROWS / BM), 512, GSMEM>>>(
        xhi, xlo, wehi, welo, nullptr, qhi, qlo, MROWS, NQKV, D_);

    sufv_partial<<<dim3(32, H_, B_), 64>>>(qhi, qlo, sufv);
    sufv_scan<<<dim3(H_, B_), 64>>>(sufv);

    attn_wmma<<<dim3(S_ / 64, H_, B_), 256, ASMEM>>>(qhi, qlo, sufv, ahi, alo);

    gemm_wmma<0><<<dim3(D_ / BN, MROWS / BM), 512, GSMEM>>>(
        ahi, alo, wohi, wolo, y, nullptr, nullptr, MROWS, D_, D_);

    ln_kernel<<<MROWS, 256>>>(x, y, gamma, beta, out);
}

// round 15
// speedup vs baseline: 1.3329x; 1.3329x over previous
#include <cuda_runtime.h>
#include <cuda_bf16.h>
#include <mma.h>
#include <cstdint>
#include <math.h>

using namespace nvcuda;

#define B_    2
#define S_    2048
#define D_    1024
#define H_    16
#define QKV_  192
#define NQKV  (H_ * QKV_)   /* 3072 */
#define MROWS (B_ * S_)     /* 4096 */

// ---------------- scratch ---------------------------------------------------
__device__ __nv_bfloat16 g_qkvhi[(size_t)MROWS * NQKV];
__device__ __nv_bfloat16 g_qkvlo[(size_t)MROWS * NQKV];
__device__ __nv_bfloat16 g_xhi[(size_t)MROWS * D_];
__device__ __nv_bfloat16 g_xlo[(size_t)MROWS * D_];
__device__ __nv_bfloat16 g_wehi[(size_t)NQKV * D_];   // [N][K]
__device__ __nv_bfloat16 g_welo[(size_t)NQKV * D_];
__device__ __nv_bfloat16 g_wohi[(size_t)D_ * D_];
__device__ __nv_bfloat16 g_wolo[(size_t)D_ * D_];
__device__ __nv_bfloat16 g_ahi[(size_t)MROWS * D_];
__device__ __nv_bfloat16 g_alo[(size_t)MROWS * D_];
__device__ float g_y[(size_t)MROWS * D_];
__device__ float g_sufv[(size_t)B_ * H_ * 33 * 64];

// ---------------- helpers ---------------------------------------------------
__device__ __forceinline__ uint32_t smem_u32(const void* p) {
    uint32_t a;
    asm("{ .reg .u64 t; cvta.to.shared.u64 t, %1; cvt.u32.u64 %0, t; }" : "=r"(a) : "l"(p));
    return a;
}
#define CP_ASYNC16(dst, src) \
    asm volatile("cp.async.cg.shared.global [%0], [%1], 16;" :: "r"(dst), "l"(src))
#define CP_COMMIT() asm volatile("cp.async.commit_group;")
#define CP_WAIT0()  asm volatile("cp.async.wait_group 0;")

#define LDSM_X4(r0, r1, r2, r3, addr) \
    asm volatile("ldmatrix.sync.aligned.m8n8.x4.shared.b16 {%0,%1,%2,%3}, [%4];" \
        : "=r"(r0), "=r"(r1), "=r"(r2), "=r"(r3) : "r"(addr))
#define LDSM_X2(r0, r1, addr) \
    asm volatile("ldmatrix.sync.aligned.m8n8.x2.shared.b16 {%0,%1}, [%2];" \
        : "=r"(r0), "=r"(r1) : "r"(addr))
#define LDSM_X2_T(r0, r1, addr) \
    asm volatile("ldmatrix.sync.aligned.m8n8.x2.trans.shared.b16 {%0,%1}, [%2];" \
        : "=r"(r0), "=r"(r1) : "r"(addr))

__device__ __forceinline__ void mma16816(float* d, const uint32_t* a,
                                         const uint32_t* b, const float* c) {
    asm volatile(
        "mma.sync.aligned.m16n8k16.row.col.f32.bf16.bf16.f32 "
        "{%0,%1,%2,%3}, {%4,%5,%6,%7}, {%8,%9}, {%10,%11,%12,%13};"
        : "=f"(d[0]), "=f"(d[1]), "=f"(d[2]), "=f"(d[3])
        : "r"(a[0]), "r"(a[1]), "r"(a[2]), "r"(a[3]),
          "r"(b[0]), "r"(b[1]),
          "f"(c[0]), "f"(c[1]), "f"(c[2]), "f"(c[3]));
}

__device__ __forceinline__ uint32_t packbf2(float x, float y) {
    __nv_bfloat162 t(__float2bfloat16(x), __float2bfloat16(y));
    return *(uint32_t*)&t;
}

// ---------------------------------------------------------------------------
// HMMA GEMM — R13 proven config: 128x128 tile, 256 thr, BK=32, 2 CTAs/SM.
// ---------------------------------------------------------------------------
#define BM 128
#define BN 128
#define BK 32
#define GP 40
#define MATB (BM * GP * 2)
#define STAGEB (4 * MATB)
#define GSMEM (2 * STAGEB)

template<int MODE>
__global__ void __launch_bounds__(256, 2) gemm_wmma(
    const __nv_bfloat16* __restrict__ Ahi, const __nv_bfloat16* __restrict__ Alo,
    const __nv_bfloat16* __restrict__ Bhi, const __nv_bfloat16* __restrict__ Blo,
    float* __restrict__ C, __nv_bfloat16* __restrict__ Chi,
    __nv_bfloat16* __restrict__ Clo, int M, int N, int K)
{
    extern __shared__ __align__(16) char smem[];
    const uint32_t sb = smem_u32(smem);
    const int tid = threadIdx.x;
    const int wid = tid >> 5;
    const int wm = wid & 3, wn = wid >> 2;
    const int m0 = blockIdx.y * BM, n0 = blockIdx.x * BN;

    wmma::fragment<wmma::accumulator, 16, 16, 16, float> acc[2][4];
#pragma unroll
    for (int i = 0; i < 2; i++)
#pragma unroll
        for (int j = 0; j < 4; j++) wmma::fill_fragment(acc[i][j], 0.0f);

    const int u0 = tid * 2;
    const int lrow = u0 >> 2;
    const int lcb = (u0 & 3) * 16;
    const char* gAh = (const char*)&Ahi[(size_t)(m0 + lrow) * K] + lcb;
    const char* gAl = (const char*)&Alo[(size_t)(m0 + lrow) * K] + lcb;
    const char* gBh = (const char*)&Bhi[(size_t)(n0 + lrow) * K] + lcb;
    const char* gBl = (const char*)&Blo[(size_t)(n0 + lrow) * K] + lcb;
    const uint32_t soff = lrow * (GP * 2) + lcb;

    const int KT = K / BK;
    auto issue = [&](int st, int kt) {
        const uint32_t base = sb + st * STAGEB + soff;
        const size_t gk = (size_t)kt * (BK * 2);
        CP_ASYNC16(base,            gAh + gk);  CP_ASYNC16(base + 16,            gAh + gk + 16);
        CP_ASYNC16(base + MATB,     gAl + gk);  CP_ASYNC16(base + MATB + 16,     gAl + gk + 16);
        CP_ASYNC16(base + 2*MATB,   gBh + gk);  CP_ASYNC16(base + 2*MATB + 16,   gBh + gk + 16);
        CP_ASYNC16(base + 3*MATB,   gBl + gk);  CP_ASYNC16(base + 3*MATB + 16,   gBl + gk + 16);
    };

    issue(0, 0);
    CP_COMMIT();

    for (int kt = 0; kt < KT; kt++) {
        const int st = kt & 1;
        CP_WAIT0();
        __syncthreads();
        if (kt + 1 < KT) { issue(st ^ 1, kt + 1); CP_COMMIT(); }

        const __nv_bfloat16* sAh = (const __nv_bfloat16*)(smem + st * STAGEB);
        const __nv_bfloat16* sAl = sAh + BM * GP;
        const __nv_bfloat16* sBh = sAl + BM * GP;
        const __nv_bfloat16* sBl = sBh + BM * GP;

#pragma unroll
        for (int kk = 0; kk < BK; kk += 16) {
            wmma::fragment<wmma::matrix_b, 16, 16, 16, __nv_bfloat16, wmma::col_major> bh[4], bl[4];
#pragma unroll
            for (int j = 0; j < 4; j++) {
                wmma::load_matrix_sync(bh[j], sBh + (wn * 64 + j * 16) * GP + kk, GP);
                wmma::load_matrix_sync(bl[j], sBl + (wn * 64 + j * 16) * GP + kk, GP);
            }
#pragma unroll
            for (int i = 0; i < 2; i++) {
                wmma::fragment<wmma::matrix_a, 16, 16, 16, __nv_bfloat16, wmma::row_major> ah, al;
                wmma::load_matrix_sync(ah, sAh + (wm * 32 + i * 16) * GP + kk, GP);
                wmma::load_matrix_sync(al, sAl + (wm * 32 + i * 16) * GP + kk, GP);
#pragma unroll
                for (int j = 0; j < 4; j++) wmma::mma_sync(acc[i][j], ah, bh[j], acc[i][j]);
#pragma unroll
                for (int j = 0; j < 4; j++) wmma::mma_sync(acc[i][j], ah, bl[j], acc[i][j]);
#pragma unroll
                for (int j = 0; j < 4; j++) wmma::mma_sync(acc[i][j], al, bh[j], acc[i][j]);
            }
        }
    }

    if (MODE == 0) {
#pragma unroll
        for (int i = 0; i < 2; i++)
#pragma unroll
            for (int j = 0; j < 4; j++)
                wmma::store_matrix_sync(
                    &C[(size_t)(m0 + wm * 32 + i * 16) * N + n0 + wn * 64 + j * 16],
                    acc[i][j], N, wmma::mem_row_major);
    } else {
        __syncthreads();
        float* stage = (float*)smem;
#pragma unroll
        for (int i = 0; i < 2; i++)
#pragma unroll
            for (int j = 0; j < 4; j++)
                wmma::store_matrix_sync(
                    &stage[(size_t)(wm * 32 + i * 16) * BN + wn * 64 + j * 16],
                    acc[i][j], BN, wmma::mem_row_major);
        __syncthreads();
#pragma unroll
        for (int it = 0; it < 16; it++) {
            const int fi = tid + it * 256;
            const int row = fi >> 5, c4 = (fi & 31) * 4;
            float4 v = *(const float4*)&stage[row * BN + c4];
            __nv_bfloat16 h0 = __float2bfloat16(v.x), h1 = __float2bfloat16(v.y);
            __nv_bfloat16 h2 = __float2bfloat16(v.z), h3 = __float2bfloat16(v.w);
            __nv_bfloat162 hA(h0, h1), hB(h2, h3);
            __nv_bfloat162 lA(__float2bfloat16(v.x - __bfloat162float(h0)),
                              __float2bfloat16(v.y - __bfloat162float(h1)));
            __nv_bfloat162 lB(__float2bfloat16(v.z - __bfloat162float(h2)),
                              __float2bfloat16(v.w - __bfloat162float(h3)));
            const size_t o = (size_t)(m0 + row) * N + n0 + c4;
            *(__nv_bfloat162*)&Chi[o] = hA; *(__nv_bfloat162*)&Chi[o + 2] = hB;
            *(__nv_bfloat162*)&Clo[o] = lA; *(__nv_bfloat162*)&Clo[o + 2] = lB;
        }
    }
}

// ---------------------------------------------------------------------------
__global__ void __launch_bounds__(256) split4(const float4* __restrict__ in,
                                              __nv_bfloat162* __restrict__ hi,
                                              __nv_bfloat162* __restrict__ lo,
                                              int n4) {
    int i = blockIdx.x * 256 + threadIdx.x;
    if (i >= n4) return;
    float4 v = in[i];
    __nv_bfloat16 h0 = __float2bfloat16(v.x), h1 = __float2bfloat16(v.y);
    __nv_bfloat16 h2 = __float2bfloat16(v.z), h3 = __float2bfloat16(v.w);
    hi[i * 2 + 0] = __nv_bfloat162(h0, h1);
    hi[i * 2 + 1] = __nv_bfloat162(h2, h3);
    lo[i * 2 + 0] = __nv_bfloat162(__float2bfloat16(v.x - __bfloat162float(h0)),
                                   __float2bfloat16(v.y - __bfloat162float(h1)));
    lo[i * 2 + 1] = __nv_bfloat162(__float2bfloat16(v.z - __bfloat162float(h2)),
                                   __float2bfloat16(v.w - __bfloat162float(h3)));
}

__global__ void __launch_bounds__(256) transpose_split(const float* __restrict__ W,
                                                       __nv_bfloat16* __restrict__ hi,
                                                       __nv_bfloat16* __restrict__ lo,
                                                       int K, int N) {
    __shared__ float t[32][33];
    const int n0 = blockIdx.x * 32, k0 = blockIdx.y * 32;
    const int x = threadIdx.x, y = threadIdx.y;
#pragma unroll
    for (int i = 0; i < 32; i += 8)
        t[y + i][x] = W[(size_t)(k0 + y + i) * N + n0 + x];
    __syncthreads();
#pragma unroll
    for (int i = 0; i < 32; i += 8) {
        float v = t[x][y + i];
        __nv_bfloat16 h = __float2bfloat16(v);
        size_t o = (size_t)(n0 + y + i) * K + k0 + x;
        hi[o] = h;
        lo[o] = __float2bfloat16(v - __bfloat162float(h));
    }
}

// ---------------------------------------------------------------------------
__global__ void __launch_bounds__(64) sufv_partial(const __nv_bfloat16* __restrict__ qhi,
                                                   const __nv_bfloat16* __restrict__ qlo,
                                                   float* __restrict__ sufv) {
    const int t = blockIdx.x, h = blockIdx.y, b = blockIdx.z, d = threadIdx.x;
    const size_t col = (size_t)h * QKV_ + 128 + d;
    float acc = 0.0f;
#pragma unroll 8
    for (int kk = 0; kk < 64; kk++) {
        const size_t o = (size_t)(b * S_ + t * 64 + kk) * NQKV + col;
        acc += __bfloat162float(qhi[o]) + __bfloat162float(qlo[o]);
    }
    sufv[((size_t)(b * H_ + h) * 33 + t) * 64 + d] = acc;
}

__global__ void __launch_bounds__(64) sufv_scan(float* __restrict__ sufv) {
    const int h = blockIdx.x, b = blockIdx.y, d = threadIdx.x;
    float* base = &sufv[((size_t)(b * H_ + h) * 33) * 64 + d];
    float acc = 0.0f;
    base[32 * 64] = 0.0f;
    for (int t = 31; t >= 0; t--) {
        acc += base[t * 64];
        base[t * 64] = acc;
    }
}

// ---------------------------------------------------------------------------
// Register-resident flash attention with mma.sync.m16n8k16 (FA2 layout).
// CTA = 128 q-rows, 8 warps (16 rows x 64 keys each), 256 threads, 2 CTAs/SM.
// Only smem: Q hi/lo + double-buffered K/V stages. One syncthreads per tile.
// ---------------------------------------------------------------------------
#define AP 72
#define AQH 0
#define AQL (AQH + 128 * AP * 2)            /* 18432 */
#define AKV (AQL + 128 * AP * 2)            /* 36864 */
#define KVMAT (64 * AP * 2)                 /* 9216  */
#define KVSTAGE (4 * KVMAT)                 /* 36864 */
#define ASMEM (AKV + 2 * KVSTAGE)           /* 110592 */

__global__ void __launch_bounds__(256, 2) attn_mma(
    const __nv_bfloat16* __restrict__ qkvhi, const __nv_bfloat16* __restrict__ qkvlo,
    const float* __restrict__ sufv,
    __nv_bfloat16* __restrict__ ahi, __nv_bfloat16* __restrict__ alo)
{
    extern __shared__ __align__(32) char smem[];
    const uint32_t sb = smem_u32(smem);

    const int tid = threadIdx.x, lane = tid & 31, w = tid >> 5;
    const int gid = lane >> 2, tig = lane & 3;
    const int qt = gridDim.x - 1 - blockIdx.x;   // heavy blocks first
    const int h = blockIdx.y, b = blockIdx.z;
    const int q0 = qt * 128;
    const size_t base = (size_t)b * S_ * NQKV + (size_t)h * QKV_;

    // load Q hi/lo (128 x 64) to smem
    __nv_bfloat16* sQh = (__nv_bfloat16*)(smem + AQH);
    __nv_bfloat16* sQl = (__nv_bfloat16*)(smem + AQL);
#pragma unroll
    for (int j = 0; j < 4; j++) {
        const int i = tid + j * 256;
        const int row = i >> 3, c8 = (i & 7) * 8;
        const size_t g = base + (size_t)(q0 + row) * NQKV + c8;
        *(uint4*)&sQh[row * AP + c8] = *(const uint4*)&qkvhi[g];
        *(uint4*)&sQl[row * AP + c8] = *(const uint4*)&qkvlo[g];
    }

    auto issue_kv = [&](int st, int kt) {
#pragma unroll
        for (int jj = 0; jj < 2; jj++) {
            const int row = (tid >> 3) + jj * 32;
            const int c8 = (tid & 7) * 8;
            const uint32_t stb = sb + AKV + st * KVSTAGE + (uint32_t)(row * AP + c8) * 2;
            const char* gh = (const char*)(qkvhi + base + (size_t)(kt * 64 + row) * NQKV + c8);
            const char* gl = (const char*)(qkvlo + base + (size_t)(kt * 64 + row) * NQKV + c8);
            CP_ASYNC16(stb,             gh + 128);   // K hi
            CP_ASYNC16(stb + KVMAT,     gl + 128);   // K lo
            CP_ASYNC16(stb + 2*KVMAT,   gh + 256);   // V hi
            CP_ASYNC16(stb + 3*KVMAT,   gl + 256);   // V lo
        }
    };

    // ldmatrix lane-address offsets (bytes)
    const int l15 = lane & 15;
    const uint32_t a_off = (uint32_t)((16 * w + (lane & 15)) * AP + 8 * (lane >> 4)) * 2;
    const uint32_t k_off = (uint32_t)((l15 & 7) * AP + 8 * (l15 >> 3)) * 2;
    const uint32_t v_off = (uint32_t)(l15 * AP) * 2;

    const int row0 = q0 + 16 * w + gid;
    const int row1 = row0 + 8;
    float oc[8][4];
#pragma unroll
    for (int j = 0; j < 8; j++)
#pragma unroll
        for (int r = 0; r < 4; r++) oc[j][r] = 0.0f;
    float m0 = -1e30f, m1 = -1e30f, l0 = 0.0f, l1 = 0.0f;
    const float scale = 0.125f;

    const int KTILES = 2 * qt + 2;
    issue_kv(0, 0);
    CP_COMMIT();

    for (int kt = 0; kt < KTILES; kt++) {
        const int st = kt & 1;
        const int k0 = kt * 64;
        CP_WAIT0();
        __syncthreads();   // stage st + (kt==0) Q visible; prev reads done
        if (kt + 1 < KTILES) { issue_kv(st ^ 1, kt + 1); CP_COMMIT(); }

        const uint32_t kb_h = sb + AKV + st * KVSTAGE;
        const uint32_t kb_l = kb_h + KVMAT;
        const uint32_t vb_h = kb_h + 2 * KVMAT;
        const uint32_t vb_l = kb_h + 3 * KVMAT;

        // ---- S = Q K^T : sc[j] covers keys [8j, 8j+8) x rows 16 ----
        float sc[8][4];
#pragma unroll
        for (int j = 0; j < 8; j++)
#pragma unroll
            for (int r = 0; r < 4; r++) sc[j][r] = 0.0f;

#pragma unroll
        for (int ks = 0; ks < 4; ks++) {
            const int kk = ks * 16;
            uint32_t qh[4], ql[4];
            LDSM_X4(qh[0], qh[1], qh[2], qh[3], sb + AQH + a_off + kk * 2);
            LDSM_X4(ql[0], ql[1], ql[2], ql[3], sb + AQL + a_off + kk * 2);
#pragma unroll
            for (int j = 0; j < 8; j++) {
                const uint32_t ka = (uint32_t)(j * 8 * AP + kk) * 2 + k_off;
                uint32_t bh[2], bl[2];
                LDSM_X2(bh[0], bh[1], kb_h + ka);
                LDSM_X2(bl[0], bl[1], kb_l + ka);
                mma16816(sc[j], qh, bh, sc[j]);
                mma16816(sc[j], qh, bl, sc[j]);
                mma16816(sc[j], ql, bh, sc[j]);
            }
        }

        // ---- mask + online softmax (all in registers) ----
        float mx0 = -1e30f, mx1 = -1e30f;
#pragma unroll
        for (int j = 0; j < 8; j++) {
#pragma unroll
            for (int e = 0; e < 2; e++) {
                const int key = k0 + 8 * j + 2 * tig + e;
                float s0 = sc[j][e] * scale;     if (key > row0) s0 = 0.0f;
                float s1 = sc[j][2 + e] * scale; if (key > row1) s1 = 0.0f;
                sc[j][e] = s0; sc[j][2 + e] = s1;
                mx0 = fmaxf(mx0, s0); mx1 = fmaxf(mx1, s1);
            }
        }
        mx0 = fmaxf(mx0, __shfl_xor_sync(0xffffffffu, mx0, 1));
        mx0 = fmaxf(mx0, __shfl_xor_sync(0xffffffffu, mx0, 2));
        mx1 = fmaxf(mx1, __shfl_xor_sync(0xffffffffu, mx1, 1));
        mx1 = fmaxf(mx1, __shfl_xor_sync(0xffffffffu, mx1, 2));
        const float mn0 = fmaxf(m0, mx0), mn1 = fmaxf(m1, mx1);
        const float al0 = __expf(m0 - mn0), al1 = __expf(m1 - mn1);
        m0 = mn0; m1 = mn1;
        float ls0 = 0.0f, ls1 = 0.0f;
#pragma unroll
        for (int j = 0; j < 8; j++) {
#pragma unroll
            for (int e = 0; e < 2; e++) {
                float p0 = __expf(sc[j][e] - mn0);
                float p1 = __expf(sc[j][2 + e] - mn1);
                sc[j][e] = p0; sc[j][2 + e] = p1;
                ls0 += p0; ls1 += p1;
            }
        }
        l0 = l0 * al0 + ls0;
        l1 = l1 * al1 + ls1;
#pragma unroll
        for (int j = 0; j < 8; j++) {
            oc[j][0] *= al0; oc[j][1] *= al0;
            oc[j][2] *= al1; oc[j][3] *= al1;
        }

        // ---- PV: repack S C-frags into A-frags (hi/lo), accumulate O ----
#pragma unroll
        for (int t = 0; t < 4; t++) {
            const int kk = t * 16;
            uint32_t pah[4], pal[4];
            {
                const float* cA = sc[2 * t];
                const float* cB = sc[2 * t + 1];
                float hA0 = __bfloat162float(__float2bfloat16(cA[0]));
                float hA1 = __bfloat162float(__float2bfloat16(cA[1]));
                float hA2 = __bfloat162float(__float2bfloat16(cA[2]));
                float hA3 = __bfloat162float(__float2bfloat16(cA[3]));
                float hB0 = __bfloat162float(__float2bfloat16(cB[0]));
                float hB1 = __bfloat162float(__float2bfloat16(cB[1]));
                float hB2 = __bfloat162float(__float2bfloat16(cB[2]));
                float hB3 = __bfloat162float(__float2bfloat16(cB[3]));
                pah[0] = packbf2(hA0, hA1);           pah[1] = packbf2(hA2, hA3);
                pah[2] = packbf2(hB0, hB1);           pah[3] = packbf2(hB2, hB3);
                pal[0] = packbf2(cA[0] - hA0, cA[1] - hA1);
                pal[1] = packbf2(cA[2] - hA2, cA[3] - hA3);
                pal[2] = packbf2(cB[0] - hB0, cB[1] - hB1);
                pal[3] = packbf2(cB[2] - hB2, cB[3] - hB3);
            }
#pragma unroll
            for (int j = 0; j < 8; j++) {
                const uint32_t va = (uint32_t)(kk * AP + j * 8) * 2 + v_off;
                uint32_t vh[2], vl[2];
                LDSM_X2_T(vh[0], vh[1], vb_h + va);
                LDSM_X2_T(vl[0], vl[1], vb_l + va);
                mma16816(oc[j], pah, vh, oc[j]);
                mma16816(oc[j], pah, vl, oc[j]);
                mma16816(oc[j], pal, vh, oc[j]);
            }
        }
    }

    // reduce l across the 4-lane row group
    l0 += __shfl_xor_sync(0xffffffffu, l0, 1);
    l0 += __shfl_xor_sync(0xffffffffu, l0, 2);
    l1 += __shfl_xor_sync(0xffffffffu, l1, 1);
    l1 += __shfl_xor_sync(0xffffffffu, l1, 2);

    // suffix keys >= 128*(qt+1): logit 0 each
    const int cnt = S_ - 128 * (qt + 1);
    if (cnt > 0) {
        const float nn0 = fmaxf(m0, 0.0f), nn1 = fmaxf(m1, 0.0f);
        const float a20 = __expf(m0 - nn0), a21 = __expf(m1 - nn1);
        const float e00 = __expf(-nn0), e01 = __expf(-nn1);
        l0 = l0 * a20 + (float)cnt * e00;
        l1 = l1 * a21 + (float)cnt * e01;
        const float* sv = &sufv[((size_t)(b * H_ + h) * 33 + 2 * (qt + 1)) * 64];
#pragma unroll
        for (int j = 0; j < 8; j++) {
#pragma unroll
            for (int e = 0; e < 2; e++) {
                const float svv = sv[8 * j + 2 * tig + e];
                oc[j][e]     = oc[j][e]     * a20 + e00 * svv;
                oc[j][2 + e] = oc[j][2 + e] * a21 + e01 * svv;
            }
        }
    }
    const float inv0 = 1.0f / l0, inv1 = 1.0f / l1;

    // store O -> ahi/alo (hi/lo split), 4B per (row, d-pair)
    const size_t ob0 = (size_t)(b * S_ + row0) * D_ + h * 64;
    const size_t ob1 = (size_t)(b * S_ + row1) * D_ + h * 64;
#pragma unroll
    for (int j = 0; j < 8; j++) {
        const int d0 = 8 * j + 2 * tig;
        float v0 = oc[j][0] * inv0, v1 = oc[j][1] * inv0;
        float v2 = oc[j][2] * inv1, v3 = oc[j][3] * inv1;
        float h0 = __bfloat162float(__float2bfloat16(v0));
        float h1 = __bfloat162float(__float2bfloat16(v1));
        float h2 = __bfloat162float(__float2bfloat16(v2));
        float h3 = __bfloat162float(__float2bfloat16(v3));
        *(uint32_t*)&ahi[ob0 + d0] = packbf2(h0, h1);
        *(uint32_t*)&alo[ob0 + d0] = packbf2(v0 - h0, v1 - h1);
        *(uint32_t*)&ahi[ob1 + d0] = packbf2(h2, h3);
        *(uint32_t*)&alo[ob1 + d0] = packbf2(v2 - h2, v3 - h3);
    }
}

// ---------------------------------------------------------------------------
__global__ void __launch_bounds__(256) ln_kernel(const float* __restrict__ x,
                                                 const float* __restrict__ y,
                                                 const float* __restrict__ gamma,
                                                 const float* __restrict__ beta,
                                                 float* __restrict__ out) {
    __shared__ float red[8];
    const int row = blockIdx.x, t = threadIdx.x;
    const int lane = t & 31, wid = t >> 5;
    const size_t off = (size_t)row * D_;

    float v[4], s = 0.0f;
#pragma unroll
    for (int i = 0; i < 4; i++) {
        int idx = t + i * 256;
        v[i] = x[off + idx] + y[off + idx];
        s += v[i];
    }
    for (int d = 16; d > 0; d >>= 1) s += __shfl_xor_sync(0xffffffffu, s, d);
    if (lane == 0) red[wid] = s;
    __syncthreads();
    float tot = 0.0f;
#pragma unroll
    for (int w = 0; w < 8; w++) tot += red[w];
    const float mean = tot * (1.0f / D_);
    __syncthreads();
    float ss = 0.0f;
#pragma unroll
    for (int i = 0; i < 4; i++) { float d = v[i] - mean; ss += d * d; }
    for (int d = 16; d > 0; d >>= 1) ss += __shfl_xor_sync(0xffffffffu, ss, d);
    if (lane == 0) red[wid] = ss;
    __syncthreads();
    float tot2 = 0.0f;
#pragma unroll
    for (int w = 0; w < 8; w++) tot2 += red[w];
    const float rstd = rsqrtf(tot2 * (1.0f / D_) + 1e-3f);
#pragma unroll
    for (int i = 0; i < 4; i++) {
        int idx = t + i * 256;
        out[off + idx] = (v[i] - mean) * rstd * gamma[idx] + beta[idx];
    }
}

// ---------------------------------------------------------------------------
extern "C" void kernel_launch(void* const* d_in, const int* in_sizes, int n_in,
                              void* d_out, int out_size) {
    const float* x       = (const float*)d_in[0];
    const float* W_embed = (const float*)d_in[2];
    const float* W_out   = (const float*)d_in[3];
    const float* gamma   = (const float*)d_in[4];
    const float* beta    = (const float*)d_in[5];
    float* out = (float*)d_out;

    __nv_bfloat16 *qhi, *qlo, *xhi, *xlo, *wehi, *welo, *wohi, *wolo, *ahi, *alo;
    float *y, *sufv;
    cudaGetSymbolAddress((void**)&qhi,  g_qkvhi);
    cudaGetSymbolAddress((void**)&qlo,  g_qkvlo);
    cudaGetSymbolAddress((void**)&xhi,  g_xhi);
    cudaGetSymbolAddress((void**)&xlo,  g_xlo);
    cudaGetSymbolAddress((void**)&wehi, g_wehi);
    cudaGetSymbolAddress((void**)&welo, g_welo);
    cudaGetSymbolAddress((void**)&wohi, g_wohi);
    cudaGetSymbolAddress((void**)&wolo, g_wolo);
    cudaGetSymbolAddress((void**)&ahi,  g_ahi);
    cudaGetSymbolAddress((void**)&alo,  g_alo);
    cudaGetSymbolAddress((void**)&y,    g_y);
    cudaGetSymbolAddress((void**)&sufv, g_sufv);

    cudaFuncSetAttribute(gemm_wmma<0>, cudaFuncAttributeMaxDynamicSharedMemorySize, GSMEM);
    cudaFuncSetAttribute(gemm_wmma<1>, cudaFuncAttributeMaxDynamicSharedMemorySize, GSMEM);
    cudaFuncSetAttribute(attn_mma, cudaFuncAttributeMaxDynamicSharedMemorySize, ASMEM);

    split4<<<(MROWS * D_ / 4 + 255) / 256, 256>>>((const float4*)x,
        (__nv_bfloat162*)xhi, (__nv_bfloat162*)xlo, MROWS * D_ / 4);
    transpose_split<<<dim3(NQKV / 32, D_ / 32), dim3(32, 8)>>>(W_embed, wehi, welo, D_, NQKV);
    transpose_split<<<dim3(D_ / 32, D_ / 32), dim3(32, 8)>>>(W_out, wohi, wolo, D_, D_);

    gemm_wmma<1><<<dim3(NQKV / BN, MROWS / BM), 256, GSMEM>>>(
        xhi, xlo, wehi, welo, nullptr, qhi, qlo, MROWS, NQKV, D_);

    sufv_partial<<<dim3(32, H_, B_), 64>>>(qhi, qlo, sufv);
    sufv_scan<<<dim3(H_, B_), 64>>>(sufv);

    // 128-row Q tiles: grid 16 x H x B
    attn_mma<<<dim3(S_ / 128, H_, B_), 256, ASMEM>>>(qhi, qlo, sufv, ahi, alo);

    gemm_wmma<0><<<dim3(D_ / BN, MROWS / BM), 256, GSMEM>>>(
        ahi, alo, wohi, wolo, y, nullptr, nullptr, MROWS, D_, D_);

    ln_kernel<<<MROWS, 256>>>(x, y, gamma, beta, out);
}

// round 16
// speedup vs baseline: 1.7206x; 1.2909x over previous
#include <cuda_runtime.h>
#include <cuda_bf16.h>
#include <cuda_fp16.h>
#include <mma.h>
#include <cstdint>
#include <math.h>

using namespace nvcuda;

#define B_    2
#define S_    2048
#define D_    1024
#define H_    16
#define QKV_  192
#define NQKV  (H_ * QKV_)   /* 3072 */
#define MROWS (B_ * S_)     /* 4096 */

// ---------------- scratch ---------------------------------------------------
__device__ __nv_bfloat16 g_qkvhi[(size_t)MROWS * NQKV];
__device__ __nv_bfloat16 g_qkvlo[(size_t)MROWS * NQKV];
__device__ __half g_x16[(size_t)MROWS * D_];
__device__ __half g_weh16[(size_t)NQKV * D_];   // [N][K] fp16 hi
__device__ __half g_wel16[(size_t)NQKV * D_];   // [N][K] fp16 lo
__device__ __half g_woh16[(size_t)D_ * D_];
__device__ __half g_wol16[(size_t)D_ * D_];
__device__ __half g_att16[(size_t)MROWS * D_];
__device__ float g_y[(size_t)MROWS * D_];
__device__ float g_sufv[(size_t)B_ * H_ * 33 * 64];

// ---------------- helpers ---------------------------------------------------
__device__ __forceinline__ uint32_t smem_u32(const void* p) {
    uint32_t a;
    asm("{ .reg .u64 t; cvta.to.shared.u64 t, %1; cvt.u32.u64 %0, t; }" : "=r"(a) : "l"(p));
    return a;
}
#define CP_ASYNC16(dst, src) \
    asm volatile("cp.async.cg.shared.global [%0], [%1], 16;" :: "r"(dst), "l"(src))
#define CP_COMMIT() asm volatile("cp.async.commit_group;")
#define CP_WAIT0()  asm volatile("cp.async.wait_group 0;")

#define LDSM_X4(r0, r1, r2, r3, addr) \
    asm volatile("ldmatrix.sync.aligned.m8n8.x4.shared.b16 {%0,%1,%2,%3}, [%4];" \
        : "=r"(r0), "=r"(r1), "=r"(r2), "=r"(r3) : "r"(addr))
#define LDSM_X2(r0, r1, addr) \
    asm volatile("ldmatrix.sync.aligned.m8n8.x2.shared.b16 {%0,%1}, [%2];" \
        : "=r"(r0), "=r"(r1) : "r"(addr))
#define LDSM_X2_T(r0, r1, addr) \
    asm volatile("ldmatrix.sync.aligned.m8n8.x2.trans.shared.b16 {%0,%1}, [%2];" \
        : "=r"(r0), "=r"(r1) : "r"(addr))

__device__ __forceinline__ void mma16816(float* d, const uint32_t* a,
                                         const uint32_t* b, const float* c) {
    asm volatile(
        "mma.sync.aligned.m16n8k16.row.col.f32.bf16.bf16.f32 "
        "{%0,%1,%2,%3}, {%4,%5,%6,%7}, {%8,%9}, {%10,%11,%12,%13};"
        : "=f"(d[0]), "=f"(d[1]), "=f"(d[2]), "=f"(d[3])
        : "r"(a[0]), "r"(a[1]), "r"(a[2]), "r"(a[3]),
          "r"(b[0]), "r"(b[1]),
          "f"(c[0]), "f"(c[1]), "f"(c[2]), "f"(c[3]));
}

__device__ __forceinline__ uint32_t packbf2(float x, float y) {
    __nv_bfloat162 t(__float2bfloat16(x), __float2bfloat16(y));
    return *(uint32_t*)&t;
}
__device__ __forceinline__ uint32_t packh2(float x, float y) {
    __half2 t(__float2half(x), __float2half(y));
    return *(uint32_t*)&t;
}

// ---------------------------------------------------------------------------
// fp16 2-product GEMM: C = A16 @ (Bhi + Blo)^T, B stored [N][K] fp16 hi/lo.
// 128x128 tile, 256 thr, BK=32, 2 CTAs/SM, one sync per K-iter.
// MODE 0: C fp32. MODE 1: C -> bf16 hi/lo split (for attention input).
// ---------------------------------------------------------------------------
#define BM 128
#define BN 128
#define BK 32
#define GP 40
#define MATB (BM * GP * 2)        /* 10240 */
#define STAGEB (3 * MATB)         /* 30720 — only A, Bh, Bl */
#define GSMEM 65536               /* 2 stages (61440) and 128x128 f32 stage */

template<int MODE>
__global__ void __launch_bounds__(256, 2) gemm_h(
    const __half* __restrict__ A,
    const __half* __restrict__ Bhi, const __half* __restrict__ Blo,
    float* __restrict__ C, __nv_bfloat16* __restrict__ Chi,
    __nv_bfloat16* __restrict__ Clo, int M, int N, int K)
{
    extern __shared__ __align__(16) char smem[];
    const uint32_t sb = smem_u32(smem);
    const int tid = threadIdx.x;
    const int wid = tid >> 5;
    const int wm = wid & 3, wn = wid >> 2;
    const int m0 = blockIdx.y * BM, n0 = blockIdx.x * BN;

    wmma::fragment<wmma::accumulator, 16, 16, 16, float> acc[2][4];
#pragma unroll
    for (int i = 0; i < 2; i++)
#pragma unroll
        for (int j = 0; j < 4; j++) wmma::fill_fragment(acc[i][j], 0.0f);

    const int u0 = tid * 2;
    const int lrow = u0 >> 2;
    const int lcb = (u0 & 3) * 16;
    const char* gA  = (const char*)&A[(size_t)(m0 + lrow) * K] + lcb;
    const char* gBh = (const char*)&Bhi[(size_t)(n0 + lrow) * K] + lcb;
    const char* gBl = (const char*)&Blo[(size_t)(n0 + lrow) * K] + lcb;
    const uint32_t soff = lrow * (GP * 2) + lcb;

    const int KT = K / BK;
    auto issue = [&](int st, int kt) {
        const uint32_t base = sb + st * STAGEB + soff;
        const size_t gk = (size_t)kt * (BK * 2);
        CP_ASYNC16(base,           gA + gk);   CP_ASYNC16(base + 16,           gA + gk + 16);
        CP_ASYNC16(base + MATB,    gBh + gk);  CP_ASYNC16(base + MATB + 16,    gBh + gk + 16);
        CP_ASYNC16(base + 2*MATB,  gBl + gk);  CP_ASYNC16(base + 2*MATB + 16,  gBl + gk + 16);
    };

    issue(0, 0);
    CP_COMMIT();

    for (int kt = 0; kt < KT; kt++) {
        const int st = kt & 1;
        CP_WAIT0();
        __syncthreads();
        if (kt + 1 < KT) { issue(st ^ 1, kt + 1); CP_COMMIT(); }

        const __half* sA  = (const __half*)(smem + st * STAGEB);
        const __half* sBh = sA + BM * GP;
        const __half* sBl = sBh + BM * GP;

#pragma unroll
        for (int kk = 0; kk < BK; kk += 16) {
            wmma::fragment<wmma::matrix_b, 16, 16, 16, __half, wmma::col_major> bh[4], bl[4];
#pragma unroll
            for (int j = 0; j < 4; j++) {
                wmma::load_matrix_sync(bh[j], sBh + (wn * 64 + j * 16) * GP + kk, GP);
                wmma::load_matrix_sync(bl[j], sBl + (wn * 64 + j * 16) * GP + kk, GP);
            }
#pragma unroll
            for (int i = 0; i < 2; i++) {
                wmma::fragment<wmma::matrix_a, 16, 16, 16, __half, wmma::row_major> ah;
                wmma::load_matrix_sync(ah, sA + (wm * 32 + i * 16) * GP + kk, GP);
#pragma unroll
                for (int j = 0; j < 4; j++) wmma::mma_sync(acc[i][j], ah, bh[j], acc[i][j]);
#pragma unroll
                for (int j = 0; j < 4; j++) wmma::mma_sync(acc[i][j], ah, bl[j], acc[i][j]);
            }
        }
    }

    if (MODE == 0) {
#pragma unroll
        for (int i = 0; i < 2; i++)
#pragma unroll
            for (int j = 0; j < 4; j++)
                wmma::store_matrix_sync(
                    &C[(size_t)(m0 + wm * 32 + i * 16) * N + n0 + wn * 64 + j * 16],
                    acc[i][j], N, wmma::mem_row_major);
    } else {
        __syncthreads();
        float* stage = (float*)smem;
#pragma unroll
        for (int i = 0; i < 2; i++)
#pragma unroll
            for (int j = 0; j < 4; j++)
                wmma::store_matrix_sync(
                    &stage[(size_t)(wm * 32 + i * 16) * BN + wn * 64 + j * 16],
                    acc[i][j], BN, wmma::mem_row_major);
        __syncthreads();
#pragma unroll
        for (int it = 0; it < 16; it++) {
            const int fi = tid + it * 256;
            const int row = fi >> 5, c4 = (fi & 31) * 4;
            float4 v = *(const float4*)&stage[row * BN + c4];
            __nv_bfloat16 h0 = __float2bfloat16(v.x), h1 = __float2bfloat16(v.y);
            __nv_bfloat16 h2 = __float2bfloat16(v.z), h3 = __float2bfloat16(v.w);
            __nv_bfloat162 hA(h0, h1), hB(h2, h3);
            __nv_bfloat162 lA(__float2bfloat16(v.x - __bfloat162float(h0)),
                              __float2bfloat16(v.y - __bfloat162float(h1)));
            __nv_bfloat162 lB(__float2bfloat16(v.z - __bfloat162float(h2)),
                              __float2bfloat16(v.w - __bfloat162float(h3)));
            const size_t o = (size_t)(m0 + row) * N + n0 + c4;
            *(__nv_bfloat162*)&Chi[o] = hA; *(__nv_bfloat162*)&Chi[o + 2] = hB;
            *(__nv_bfloat162*)&Clo[o] = lA; *(__nv_bfloat162*)&Clo[o + 2] = lB;
        }
    }
}

// ---------------------------------------------------------------------------
// f32 -> fp16 convert (vectorized by 4)
// ---------------------------------------------------------------------------
__global__ void __launch_bounds__(256) convert4(const float4* __restrict__ in,
                                                __half2* __restrict__ out, int n4) {
    int i = blockIdx.x * 256 + threadIdx.x;
    if (i >= n4) return;
    float4 v = in[i];
    out[i * 2 + 0] = __half2(__float2half(v.x), __float2half(v.y));
    out[i * 2 + 1] = __half2(__float2half(v.z), __float2half(v.w));
}

// ---------------------------------------------------------------------------
// W[K,N] f32 -> fp16 hi/lo [N,K]
// ---------------------------------------------------------------------------
__global__ void __launch_bounds__(256) transpose_split16(const float* __restrict__ W,
                                                         __half* __restrict__ hi,
                                                         __half* __restrict__ lo,
                                                         int K, int N) {
    __shared__ float t[32][33];
    const int n0 = blockIdx.x * 32, k0 = blockIdx.y * 32;
    const int x = threadIdx.x, y = threadIdx.y;
#pragma unroll
    for (int i = 0; i < 32; i += 8)
        t[y + i][x] = W[(size_t)(k0 + y + i) * N + n0 + x];
    __syncthreads();
#pragma unroll
    for (int i = 0; i < 32; i += 8) {
        float v = t[x][y + i];
        __half h = __float2half(v);
        size_t o = (size_t)(n0 + y + i) * K + k0 + x;
        hi[o] = h;
        lo[o] = __float2half(v - __half2float(h));
    }
}

// ---------------------------------------------------------------------------
__global__ void __launch_bounds__(64) sufv_partial(const __nv_bfloat16* __restrict__ qhi,
                                                   const __nv_bfloat16* __restrict__ qlo,
                                                   float* __restrict__ sufv) {
    const int t = blockIdx.x, h = blockIdx.y, b = blockIdx.z, d = threadIdx.x;
    const size_t col = (size_t)h * QKV_ + 128 + d;
    float acc = 0.0f;
#pragma unroll 8
    for (int kk = 0; kk < 64; kk++) {
        const size_t o = (size_t)(b * S_ + t * 64 + kk) * NQKV + col;
        acc += __bfloat162float(qhi[o]) + __bfloat162float(qlo[o]);
    }
    sufv[((size_t)(b * H_ + h) * 33 + t) * 64 + d] = acc;
}

__global__ void __launch_bounds__(64) sufv_scan(float* __restrict__ sufv) {
    const int h = blockIdx.x, b = blockIdx.y, d = threadIdx.x;
    float* base = &sufv[((size_t)(b * H_ + h) * 33) * 64 + d];
    float acc = 0.0f;
    base[32 * 64] = 0.0f;
    for (int t = 31; t >= 0; t--) {
        acc += base[t * 64];
        base[t * 64] = acc;
    }
}

// ---------------------------------------------------------------------------
// Register-resident flash attention (R15 proven). Output stored as fp16
// single array (GEMM2 consumes A unsplit now).
// ---------------------------------------------------------------------------
#define AP 72
#define AQH 0
#define AQL (AQH + 128 * AP * 2)
#define AKV (AQL + 128 * AP * 2)
#define KVMAT (64 * AP * 2)
#define KVSTAGE (4 * KVMAT)
#define ASMEM (AKV + 2 * KVSTAGE)

__global__ void __launch_bounds__(256, 2) attn_mma(
    const __nv_bfloat16* __restrict__ qkvhi, const __nv_bfloat16* __restrict__ qkvlo,
    const float* __restrict__ sufv, __half* __restrict__ att16)
{
    extern __shared__ __align__(32) char smem[];
    const uint32_t sb = smem_u32(smem);

    const int tid = threadIdx.x, lane = tid & 31, w = tid >> 5;
    const int gid = lane >> 2, tig = lane & 3;
    const int qt = gridDim.x - 1 - blockIdx.x;
    const int h = blockIdx.y, b = blockIdx.z;
    const int q0 = qt * 128;
    const size_t base = (size_t)b * S_ * NQKV + (size_t)h * QKV_;

    __nv_bfloat16* sQh = (__nv_bfloat16*)(smem + AQH);
    __nv_bfloat16* sQl = (__nv_bfloat16*)(smem + AQL);
#pragma unroll
    for (int j = 0; j < 4; j++) {
        const int i = tid + j * 256;
        const int row = i >> 3, c8 = (i & 7) * 8;
        const size_t g = base + (size_t)(q0 + row) * NQKV + c8;
        *(uint4*)&sQh[row * AP + c8] = *(const uint4*)&qkvhi[g];
        *(uint4*)&sQl[row * AP + c8] = *(const uint4*)&qkvlo[g];
    }

    auto issue_kv = [&](int st, int kt) {
#pragma unroll
        for (int jj = 0; jj < 2; jj++) {
            const int row = (tid >> 3) + jj * 32;
            const int c8 = (tid & 7) * 8;
            const uint32_t stb = sb + AKV + st * KVSTAGE + (uint32_t)(row * AP + c8) * 2;
            const char* gh = (const char*)(qkvhi + base + (size_t)(kt * 64 + row) * NQKV + c8);
            const char* gl = (const char*)(qkvlo + base + (size_t)(kt * 64 + row) * NQKV + c8);
            CP_ASYNC16(stb,             gh + 128);
            CP_ASYNC16(stb + KVMAT,     gl + 128);
            CP_ASYNC16(stb + 2*KVMAT,   gh + 256);
            CP_ASYNC16(stb + 3*KVMAT,   gl + 256);
        }
    };

    const int l15 = lane & 15;
    const uint32_t a_off = (uint32_t)((16 * w + (lane & 15)) * AP + 8 * (lane >> 4)) * 2;
    const uint32_t k_off = (uint32_t)((l15 & 7) * AP + 8 * (l15 >> 3)) * 2;
    const uint32_t v_off = (uint32_t)(l15 * AP) * 2;

    const int row0 = q0 + 16 * w + gid;
    const int row1 = row0 + 8;
    float oc[8][4];
#pragma unroll
    for (int j = 0; j < 8; j++)
#pragma unroll
        for (int r = 0; r < 4; r++) oc[j][r] = 0.0f;
    float m0 = -1e30f, m1 = -1e30f, l0 = 0.0f, l1 = 0.0f;
    const float scale = 0.125f;

    const int KTILES = 2 * qt + 2;
    issue_kv(0, 0);
    CP_COMMIT();

    for (int kt = 0; kt < KTILES; kt++) {
        const int st = kt & 1;
        const int k0 = kt * 64;
        CP_WAIT0();
        __syncthreads();
        if (kt + 1 < KTILES) { issue_kv(st ^ 1, kt + 1); CP_COMMIT(); }

        const uint32_t kb_h = sb + AKV + st * KVSTAGE;
        const uint32_t kb_l = kb_h + KVMAT;
        const uint32_t vb_h = kb_h + 2 * KVMAT;
        const uint32_t vb_l = kb_h + 3 * KVMAT;

        float sc[8][4];
#pragma unroll
        for (int j = 0; j < 8; j++)
#pragma unroll
            for (int r = 0; r < 4; r++) sc[j][r] = 0.0f;

#pragma unroll
        for (int ks = 0; ks < 4; ks++) {
            const int kk = ks * 16;
            uint32_t qh[4], ql[4];
            LDSM_X4(qh[0], qh[1], qh[2], qh[3], sb + AQH + a_off + kk * 2);
            LDSM_X4(ql[0], ql[1], ql[2], ql[3], sb + AQL + a_off + kk * 2);
#pragma unroll
            for (int j = 0; j < 8; j++) {
                const uint32_t ka = (uint32_t)(j * 8 * AP + kk) * 2 + k_off;
                uint32_t bh[2], bl[2];
                LDSM_X2(bh[0], bh[1], kb_h + ka);
                LDSM_X2(bl[0], bl[1], kb_l + ka);
                mma16816(sc[j], qh, bh, sc[j]);
                mma16816(sc[j], qh, bl, sc[j]);
                mma16816(sc[j], ql, bh, sc[j]);
            }
        }

        float mx0 = -1e30f, mx1 = -1e30f;
#pragma unroll
        for (int j = 0; j < 8; j++) {
#pragma unroll
            for (int e = 0; e < 2; e++) {
                const int key = k0 + 8 * j + 2 * tig + e;
                float s0 = sc[j][e] * scale;     if (key > row0) s0 = 0.0f;
                float s1 = sc[j][2 + e] * scale; if (key > row1) s1 = 0.0f;
                sc[j][e] = s0; sc[j][2 + e] = s1;
                mx0 = fmaxf(mx0, s0); mx1 = fmaxf(mx1, s1);
            }
        }
        mx0 = fmaxf(mx0, __shfl_xor_sync(0xffffffffu, mx0, 1));
        mx0 = fmaxf(mx0, __shfl_xor_sync(0xffffffffu, mx0, 2));
        mx1 = fmaxf(mx1, __shfl_xor_sync(0xffffffffu, mx1, 1));
        mx1 = fmaxf(mx1, __shfl_xor_sync(0xffffffffu, mx1, 2));
        const float mn0 = fmaxf(m0, mx0), mn1 = fmaxf(m1, mx1);
        const float al0 = __expf(m0 - mn0), al1 = __expf(m1 - mn1);
        m0 = mn0; m1 = mn1;
        float ls0 = 0.0f, ls1 = 0.0f;
#pragma unroll
        for (int j = 0; j < 8; j++) {
#pragma unroll
            for (int e = 0; e < 2; e++) {
                float p0 = __expf(sc[j][e] - mn0);
                float p1 = __expf(sc[j][2 + e] - mn1);
                sc[j][e] = p0; sc[j][2 + e] = p1;
                ls0 += p0; ls1 += p1;
            }
        }
        l0 = l0 * al0 + ls0;
        l1 = l1 * al1 + ls1;
#pragma unroll
        for (int j = 0; j < 8; j++) {
            oc[j][0] *= al0; oc[j][1] *= al0;
            oc[j][2] *= al1; oc[j][3] *= al1;
        }

#pragma unroll
        for (int t = 0; t < 4; t++) {
            const int kk = t * 16;
            uint32_t pah[4], pal[4];
            {
                const float* cA = sc[2 * t];
                const float* cB = sc[2 * t + 1];
                float hA0 = __bfloat162float(__float2bfloat16(cA[0]));
                float hA1 = __bfloat162float(__float2bfloat16(cA[1]));
                float hA2 = __bfloat162float(__float2bfloat16(cA[2]));
                float hA3 = __bfloat162float(__float2bfloat16(cA[3]));
                float hB0 = __bfloat162float(__float2bfloat16(cB[0]));
                float hB1 = __bfloat162float(__float2bfloat16(cB[1]));
                float hB2 = __bfloat162float(__float2bfloat16(cB[2]));
                float hB3 = __bfloat162float(__float2bfloat16(cB[3]));
                pah[0] = packbf2(hA0, hA1);           pah[1] = packbf2(hA2, hA3);
                pah[2] = packbf2(hB0, hB1);           pah[3] = packbf2(hB2, hB3);
                pal[0] = packbf2(cA[0] - hA0, cA[1] - hA1);
                pal[1] = packbf2(cA[2] - hA2, cA[3] - hA3);
                pal[2] = packbf2(cB[0] - hB0, cB[1] - hB1);
                pal[3] = packbf2(cB[2] - hB2, cB[3] - hB3);
            }
#pragma unroll
            for (int j = 0; j < 8; j++) {
                const uint32_t va = (uint32_t)(kk * AP + j * 8) * 2 + v_off;
                uint32_t vh[2], vl[2];
                LDSM_X2_T(vh[0], vh[1], vb_h + va);
                LDSM_X2_T(vl[0], vl[1], vb_l + va);
                mma16816(oc[j], pah, vh, oc[j]);
                mma16816(oc[j], pah, vl, oc[j]);
                mma16816(oc[j], pal, vh, oc[j]);
            }
        }
    }

    l0 += __shfl_xor_sync(0xffffffffu, l0, 1);
    l0 += __shfl_xor_sync(0xffffffffu, l0, 2);
    l1 += __shfl_xor_sync(0xffffffffu, l1, 1);
    l1 += __shfl_xor_sync(0xffffffffu, l1, 2);

    const int cnt = S_ - 128 * (qt + 1);
    if (cnt > 0) {
        const float nn0 = fmaxf(m0, 0.0f), nn1 = fmaxf(m1, 0.0f);
        const float a20 = __expf(m0 - nn0), a21 = __expf(m1 - nn1);
        const float e00 = __expf(-nn0), e01 = __expf(-nn1);
        l0 = l0 * a20 + (float)cnt * e00;
        l1 = l1 * a21 + (float)cnt * e01;
        const float* sv = &sufv[((size_t)(b * H_ + h) * 33 + 2 * (qt + 1)) * 64];
#pragma unroll
        for (int j = 0; j < 8; j++) {
#pragma unroll
            for (int e = 0; e < 2; e++) {
                const float svv = sv[8 * j + 2 * tig + e];
                oc[j][e]     = oc[j][e]     * a20 + e00 * svv;
                oc[j][2 + e] = oc[j][2 + e] * a21 + e01 * svv;
            }
        }
    }
    const float inv0 = 1.0f / l0, inv1 = 1.0f / l1;

    const size_t ob0 = (size_t)(b * S_ + row0) * D_ + h * 64;
    const size_t ob1 = (size_t)(b * S_ + row1) * D_ + h * 64;
#pragma unroll
    for (int j = 0; j < 8; j++) {
        const int d0 = 8 * j + 2 * tig;
        *(uint32_t*)&att16[ob0 + d0] = packh2(oc[j][0] * inv0, oc[j][1] * inv0);
        *(uint32_t*)&att16[ob1 + d0] = packh2(oc[j][2] * inv1, oc[j][3] * inv1);
    }
}

// ---------------------------------------------------------------------------
__global__ void __launch_bounds__(256) ln_kernel(const float* __restrict__ x,
                                                 const float* __restrict__ y,
                                                 const float* __restrict__ gamma,
                                                 const float* __restrict__ beta,
                                                 float* __restrict__ out) {
    __shared__ float red[8];
    const int row = blockIdx.x, t = threadIdx.x;
    const int lane = t & 31, wid = t >> 5;
    const size_t off = (size_t)row * D_;

    float v[4], s = 0.0f;
#pragma unroll
    for (int i = 0; i < 4; i++) {
        int idx = t + i * 256;
        v[i] = x[off + idx] + y[off + idx];
        s += v[i];
    }
    for (int d = 16; d > 0; d >>= 1) s += __shfl_xor_sync(0xffffffffu, s, d);
    if (lane == 0) red[wid] = s;
    __syncthreads();
    float tot = 0.0f;
#pragma unroll
    for (int w = 0; w < 8; w++) tot += red[w];
    const float mean = tot * (1.0f / D_);
    __syncthreads();
    float ss = 0.0f;
#pragma unroll
    for (int i = 0; i < 4; i++) { float d = v[i] - mean; ss += d * d; }
    for (int d = 16; d > 0; d >>= 1) ss += __shfl_xor_sync(0xffffffffu, ss, d);
    if (lane == 0) red[wid] = ss;
    __syncthreads();
    float tot2 = 0.0f;
#pragma unroll
    for (int w = 0; w < 8; w++) tot2 += red[w];
    const float rstd = rsqrtf(tot2 * (1.0f / D_) + 1e-3f);
#pragma unroll
    for (int i = 0; i < 4; i++) {
        int idx = t + i * 256;
        out[off + idx] = (v[i] - mean) * rstd * gamma[idx] + beta[idx];
    }
}

// ---------------------------------------------------------------------------
extern "C" void kernel_launch(void* const* d_in, const int* in_sizes, int n_in,
                              void* d_out, int out_size) {
    const float* x       = (const float*)d_in[0];
    const float* W_embed = (const float*)d_in[2];
    const float* W_out   = (const float*)d_in[3];
    const float* gamma   = (const float*)d_in[4];
    const float* beta    = (const float*)d_in[5];
    float* out = (float*)d_out;

    __nv_bfloat16 *qhi, *qlo;
    __half *x16, *weh, *wel, *woh, *wol, *att16;
    float *y, *sufv;
    cudaGetSymbolAddress((void**)&qhi,   g_qkvhi);
    cudaGetSymbolAddress((void**)&qlo,   g_qkvlo);
    cudaGetSymbolAddress((void**)&x16,   g_x16);
    cudaGetSymbolAddress((void**)&weh,   g_weh16);
    cudaGetSymbolAddress((void**)&wel,   g_wel16);
    cudaGetSymbolAddress((void**)&woh,   g_woh16);
    cudaGetSymbolAddress((void**)&wol,   g_wol16);
    cudaGetSymbolAddress((void**)&att16, g_att16);
    cudaGetSymbolAddress((void**)&y,     g_y);
    cudaGetSymbolAddress((void**)&sufv,  g_sufv);

    cudaFuncSetAttribute(gemm_h<0>, cudaFuncAttributeMaxDynamicSharedMemorySize, GSMEM);
    cudaFuncSetAttribute(gemm_h<1>, cudaFuncAttributeMaxDynamicSharedMemorySize, GSMEM);
    cudaFuncSetAttribute(attn_mma, cudaFuncAttributeMaxDynamicSharedMemorySize, ASMEM);

    // 0) converts / transposes (fp16)
    convert4<<<(MROWS * D_ / 4 + 255) / 256, 256>>>((const float4*)x, (__half2*)x16,
                                                    MROWS * D_ / 4);
    transpose_split16<<<dim3(NQKV / 32, D_ / 32), dim3(32, 8)>>>(W_embed, weh, wel, D_, NQKV);
    transpose_split16<<<dim3(D_ / 32, D_ / 32), dim3(32, 8)>>>(W_out, woh, wol, D_, D_);

    // 1) qkv = x16 @ (Wh+Wl) -> bf16 hi/lo for attention
    gemm_h<1><<<dim3(NQKV / BN, MROWS / BM), 256, GSMEM>>>(
        x16, weh, wel, nullptr, qhi, qlo, MROWS, NQKV, D_);

    // 1b) suffix colsum of V
    sufv_partial<<<dim3(32, H_, B_), 64>>>(qhi, qlo, sufv);
    sufv_scan<<<dim3(H_, B_), 64>>>(sufv);

    // 2) attention -> fp16 single att
    attn_mma<<<dim3(S_ / 128, H_, B_), 256, ASMEM>>>(qhi, qlo, sufv, att16);

    // 3) y = att16 @ (Woh+Wol)
    gemm_h<0><<<dim3(D_ / BN, MROWS / BM), 256, GSMEM>>>(
        att16, woh, wol, y, nullptr, nullptr, MROWS, D_, D_);

    // 4) out = LN(x + y)
    ln_kernel<<<MROWS, 256>>>(x, y, gamma, beta, out);
}

// round 17
// speedup vs baseline: 1.9654x; 1.1422x over previous
#include <cuda_runtime.h>
#include <cuda_bf16.h>
#include <cuda_fp16.h>
#include <mma.h>
#include <cstdint>
#include <math.h>

using namespace nvcuda;

#define B_    2
#define S_    2048
#define D_    1024
#define H_    16
#define QKV_  192
#define NQKV  (H_ * QKV_)   /* 3072 */
#define MROWS (B_ * S_)     /* 4096 */

// ---------------- scratch ---------------------------------------------------
__device__ __half g_qkvhi[(size_t)MROWS * NQKV];
__device__ __half g_qkvlo[(size_t)MROWS * NQKV];
__device__ __half g_x16[(size_t)MROWS * D_];
__device__ __half g_weh16[(size_t)NQKV * D_];
__device__ __half g_wel16[(size_t)NQKV * D_];
__device__ __half g_woh16[(size_t)D_ * D_];
__device__ __half g_wol16[(size_t)D_ * D_];
__device__ __half g_att16[(size_t)MROWS * D_];
__device__ float g_y[(size_t)MROWS * D_];
__device__ float g_sufv[(size_t)B_ * H_ * 33 * 64];

// ---------------- helpers ---------------------------------------------------
__device__ __forceinline__ uint32_t smem_u32(const void* p) {
    uint32_t a;
    asm("{ .reg .u64 t; cvta.to.shared.u64 t, %1; cvt.u32.u64 %0, t; }" : "=r"(a) : "l"(p));
    return a;
}
#define CP_ASYNC16(dst, src) \
    asm volatile("cp.async.cg.shared.global [%0], [%1], 16;" :: "r"(dst), "l"(src))
#define CP_COMMIT() asm volatile("cp.async.commit_group;")
#define CP_WAIT0()  asm volatile("cp.async.wait_group 0;")

#define LDSM_X4(r0, r1, r2, r3, addr) \
    asm volatile("ldmatrix.sync.aligned.m8n8.x4.shared.b16 {%0,%1,%2,%3}, [%4];" \
        : "=r"(r0), "=r"(r1), "=r"(r2), "=r"(r3) : "r"(addr))
#define LDSM_X2(r0, r1, addr) \
    asm volatile("ldmatrix.sync.aligned.m8n8.x2.shared.b16 {%0,%1}, [%2];" \
        : "=r"(r0), "=r"(r1) : "r"(addr))
#define LDSM_X2_T(r0, r1, addr) \
    asm volatile("ldmatrix.sync.aligned.m8n8.x2.trans.shared.b16 {%0,%1}, [%2];" \
        : "=r"(r0), "=r"(r1) : "r"(addr))

__device__ __forceinline__ void mma16816h(float* d, const uint32_t* a,
                                          const uint32_t* b, const float* c) {
    asm volatile(
        "mma.sync.aligned.m16n8k16.row.col.f32.f16.f16.f32 "
        "{%0,%1,%2,%3}, {%4,%5,%6,%7}, {%8,%9}, {%10,%11,%12,%13};"
        : "=f"(d[0]), "=f"(d[1]), "=f"(d[2]), "=f"(d[3])
        : "r"(a[0]), "r"(a[1]), "r"(a[2]), "r"(a[3]),
          "r"(b[0]), "r"(b[1]),
          "f"(c[0]), "f"(c[1]), "f"(c[2]), "f"(c[3]));
}

__device__ __forceinline__ uint32_t packh2(float x, float y) {
    __half2 t(__float2half(x), __float2half(y));
    return *(uint32_t*)&t;
}

// ---------------------------------------------------------------------------
// fp16 2-product GEMM (R16 proven): 128x128 tile, 256 thr, BK=32, 2 CTAs/SM.
// MODE 0: C fp32. MODE 1: C -> fp16 hi/lo split (for attention input).
// ---------------------------------------------------------------------------
#define BM 128
#define BN 128
#define BK 32
#define GP 40
#define MATB (BM * GP * 2)        /* 10240 */
#define STAGEB (3 * MATB)         /* 30720 */
#define GSMEM 65536

template<int MODE>
__global__ void __launch_bounds__(256, 2) gemm_h(
    const __half* __restrict__ A,
    const __half* __restrict__ Bhi, const __half* __restrict__ Blo,
    float* __restrict__ C, __half* __restrict__ Chi,
    __half* __restrict__ Clo, int M, int N, int K)
{
    extern __shared__ __align__(16) char smem[];
    const uint32_t sb = smem_u32(smem);
    const int tid = threadIdx.x;
    const int wid = tid >> 5;
    const int wm = wid & 3, wn = wid >> 2;
    const int m0 = blockIdx.y * BM, n0 = blockIdx.x * BN;

    wmma::fragment<wmma::accumulator, 16, 16, 16, float> acc[2][4];
#pragma unroll
    for (int i = 0; i < 2; i++)
#pragma unroll
        for (int j = 0; j < 4; j++) wmma::fill_fragment(acc[i][j], 0.0f);

    const int u0 = tid * 2;
    const int lrow = u0 >> 2;
    const int lcb = (u0 & 3) * 16;
    const char* gA  = (const char*)&A[(size_t)(m0 + lrow) * K] + lcb;
    const char* gBh = (const char*)&Bhi[(size_t)(n0 + lrow) * K] + lcb;
    const char* gBl = (const char*)&Blo[(size_t)(n0 + lrow) * K] + lcb;
    const uint32_t soff = lrow * (GP * 2) + lcb;

    const int KT = K / BK;
    auto issue = [&](int st, int kt) {
        const uint32_t base = sb + st * STAGEB + soff;
        const size_t gk = (size_t)kt * (BK * 2);
        CP_ASYNC16(base,           gA + gk);   CP_ASYNC16(base + 16,           gA + gk + 16);
        CP_ASYNC16(base + MATB,    gBh + gk);  CP_ASYNC16(base + MATB + 16,    gBh + gk + 16);
        CP_ASYNC16(base + 2*MATB,  gBl + gk);  CP_ASYNC16(base + 2*MATB + 16,  gBl + gk + 16);
    };

    issue(0, 0);
    CP_COMMIT();

    for (int kt = 0; kt < KT; kt++) {
        const int st = kt & 1;
        CP_WAIT0();
        __syncthreads();
        if (kt + 1 < KT) { issue(st ^ 1, kt + 1); CP_COMMIT(); }

        const __half* sA  = (const __half*)(smem + st * STAGEB);
        const __half* sBh = sA + BM * GP;
        const __half* sBl = sBh + BM * GP;

#pragma unroll
        for (int kk = 0; kk < BK; kk += 16) {
            wmma::fragment<wmma::matrix_b, 16, 16, 16, __half, wmma::col_major> bh[4], bl[4];
#pragma unroll
            for (int j = 0; j < 4; j++) {
                wmma::load_matrix_sync(bh[j], sBh + (wn * 64 + j * 16) * GP + kk, GP);
                wmma::load_matrix_sync(bl[j], sBl + (wn * 64 + j * 16) * GP + kk, GP);
            }
#pragma unroll
            for (int i = 0; i < 2; i++) {
                wmma::fragment<wmma::matrix_a, 16, 16, 16, __half, wmma::row_major> ah;
                wmma::load_matrix_sync(ah, sA + (wm * 32 + i * 16) * GP + kk, GP);
#pragma unroll
                for (int j = 0; j < 4; j++) wmma::mma_sync(acc[i][j], ah, bh[j], acc[i][j]);
#pragma unroll
                for (int j = 0; j < 4; j++) wmma::mma_sync(acc[i][j], ah, bl[j], acc[i][j]);
            }
        }
    }

    if (MODE == 0) {
#pragma unroll
        for (int i = 0; i < 2; i++)
#pragma unroll
            for (int j = 0; j < 4; j++)
                wmma::store_matrix_sync(
                    &C[(size_t)(m0 + wm * 32 + i * 16) * N + n0 + wn * 64 + j * 16],
                    acc[i][j], N, wmma::mem_row_major);
    } else {
        __syncthreads();
        float* stage = (float*)smem;
#pragma unroll
        for (int i = 0; i < 2; i++)
#pragma unroll
            for (int j = 0; j < 4; j++)
                wmma::store_matrix_sync(
                    &stage[(size_t)(wm * 32 + i * 16) * BN + wn * 64 + j * 16],
                    acc[i][j], BN, wmma::mem_row_major);
        __syncthreads();
#pragma unroll
        for (int it = 0; it < 16; it++) {
            const int fi = tid + it * 256;
            const int row = fi >> 5, c4 = (fi & 31) * 4;
            float4 v = *(const float4*)&stage[row * BN + c4];
            __half h0 = __float2half(v.x), h1 = __float2half(v.y);
            __half h2 = __float2half(v.z), h3 = __float2half(v.w);
            __half2 hA(h0, h1), hB(h2, h3);
            __half2 lA(__float2half(v.x - __half2float(h0)),
                       __float2half(v.y - __half2float(h1)));
            __half2 lB(__float2half(v.z - __half2float(h2)),
                       __float2half(v.w - __half2float(h3)));
            const size_t o = (size_t)(m0 + row) * N + n0 + c4;
            *(__half2*)&Chi[o] = hA; *(__half2*)&Chi[o + 2] = hB;
            *(__half2*)&Clo[o] = lA; *(__half2*)&Clo[o + 2] = lB;
        }
    }
}

// ---------------------------------------------------------------------------
__global__ void __launch_bounds__(256) convert4(const float4* __restrict__ in,
                                                __half2* __restrict__ out, int n4) {
    int i = blockIdx.x * 256 + threadIdx.x;
    if (i >= n4) return;
    float4 v = in[i];
    out[i * 2 + 0] = __half2(__float2half(v.x), __float2half(v.y));
    out[i * 2 + 1] = __half2(__float2half(v.z), __float2half(v.w));
}

__global__ void __launch_bounds__(256) transpose_split16(const float* __restrict__ W,
                                                         __half* __restrict__ hi,
                                                         __half* __restrict__ lo,
                                                         int K, int N) {
    __shared__ float t[32][33];
    const int n0 = blockIdx.x * 32, k0 = blockIdx.y * 32;
    const int x = threadIdx.x, y = threadIdx.y;
#pragma unroll
    for (int i = 0; i < 32; i += 8)
        t[y + i][x] = W[(size_t)(k0 + y + i) * N + n0 + x];
    __syncthreads();
#pragma unroll
    for (int i = 0; i < 32; i += 8) {
        float v = t[x][y + i];
        __half h = __float2half(v);
        size_t o = (size_t)(n0 + y + i) * K + k0 + x;
        hi[o] = h;
        lo[o] = __float2half(v - __half2float(h));
    }
}

// ---------------------------------------------------------------------------
__global__ void __launch_bounds__(64) sufv_partial(const __half* __restrict__ qhi,
                                                   const __half* __restrict__ qlo,
                                                   float* __restrict__ sufv) {
    const int t = blockIdx.x, h = blockIdx.y, b = blockIdx.z, d = threadIdx.x;
    const size_t col = (size_t)h * QKV_ + 128 + d;
    float acc = 0.0f;
#pragma unroll 8
    for (int kk = 0; kk < 64; kk++) {
        const size_t o = (size_t)(b * S_ + t * 64 + kk) * NQKV + col;
        acc += __half2float(qhi[o]) + __half2float(qlo[o]);
    }
    sufv[((size_t)(b * H_ + h) * 33 + t) * 64 + d] = acc;
}

__global__ void __launch_bounds__(64) sufv_scan(float* __restrict__ sufv) {
    const int h = blockIdx.x, b = blockIdx.y, d = threadIdx.x;
    float* base = &sufv[((size_t)(b * H_ + h) * 33) * 64 + d];
    float acc = 0.0f;
    base[32 * 64] = 0.0f;
    for (int t = 31; t >= 0; t--) {
        acc += base[t * 64];
        base[t * 64] = acc;
    }
}

// ---------------------------------------------------------------------------
// Register-resident flash attention, fp16 2-product:
// S = Qhi * (Khi + Klo),  O += P16 * (Vhi + Vlo).  80 MMAs/tile (was 120).
// smem: Q (18432) + 2 KV stages (73728) = 92160 -> 2 CTAs/SM.
// ---------------------------------------------------------------------------
#define AP 72
#define AQ 0
#define AKV (AQ + 128 * AP * 2)             /* 18432 */
#define KVMAT (64 * AP * 2)                 /* 9216  */
#define KVSTAGE (4 * KVMAT)                 /* 36864 */
#define ASMEM (AKV + 2 * KVSTAGE)           /* 92160 */

__global__ void __launch_bounds__(256, 2) attn_mma(
    const __half* __restrict__ qkvhi, const __half* __restrict__ qkvlo,
    const float* __restrict__ sufv, __half* __restrict__ att16)
{
    extern __shared__ __align__(32) char smem[];
    const uint32_t sb = smem_u32(smem);

    const int tid = threadIdx.x, lane = tid & 31, w = tid >> 5;
    const int gid = lane >> 2, tig = lane & 3;
    const int qt = gridDim.x - 1 - blockIdx.x;
    const int h = blockIdx.y, b = blockIdx.z;
    const int q0 = qt * 128;
    const size_t base = (size_t)b * S_ * NQKV + (size_t)h * QKV_;

    // load Q (hi only) 128 x 64
    __half* sQ = (__half*)(smem + AQ);
#pragma unroll
    for (int j = 0; j < 4; j++) {
        const int i = tid + j * 256;
        const int row = i >> 3, c8 = (i & 7) * 8;
        *(uint4*)&sQ[row * AP + c8] =
            *(const uint4*)&qkvhi[base + (size_t)(q0 + row) * NQKV + c8];
    }

    auto issue_kv = [&](int st, int kt) {
#pragma unroll
        for (int jj = 0; jj < 2; jj++) {
            const int row = (tid >> 3) + jj * 32;
            const int c8 = (tid & 7) * 8;
            const uint32_t stb = sb + AKV + st * KVSTAGE + (uint32_t)(row * AP + c8) * 2;
            const char* gh = (const char*)(qkvhi + base + (size_t)(kt * 64 + row) * NQKV + c8);
            const char* gl = (const char*)(qkvlo + base + (size_t)(kt * 64 + row) * NQKV + c8);
            CP_ASYNC16(stb,             gh + 128);   // K hi
            CP_ASYNC16(stb + KVMAT,     gl + 128);   // K lo
            CP_ASYNC16(stb + 2*KVMAT,   gh + 256);   // V hi
            CP_ASYNC16(stb + 3*KVMAT,   gl + 256);   // V lo
        }
    };

    const int l15 = lane & 15;
    const uint32_t a_off = (uint32_t)((16 * w + (lane & 15)) * AP + 8 * (lane >> 4)) * 2;
    const uint32_t k_off = (uint32_t)((l15 & 7) * AP + 8 * (l15 >> 3)) * 2;
    const uint32_t v_off = (uint32_t)(l15 * AP) * 2;

    const int row0 = q0 + 16 * w + gid;
    const int row1 = row0 + 8;
    float oc[8][4];
#pragma unroll
    for (int j = 0; j < 8; j++)
#pragma unroll
        for (int r = 0; r < 4; r++) oc[j][r] = 0.0f;
    float m0 = -1e30f, m1 = -1e30f, l0 = 0.0f, l1 = 0.0f;
    const float scale = 0.125f;

    const int KTILES = 2 * qt + 2;
    issue_kv(0, 0);
    CP_COMMIT();

    for (int kt = 0; kt < KTILES; kt++) {
        const int st = kt & 1;
        const int k0 = kt * 64;
        CP_WAIT0();
        __syncthreads();
        if (kt + 1 < KTILES) { issue_kv(st ^ 1, kt + 1); CP_COMMIT(); }

        const uint32_t kb_h = sb + AKV + st * KVSTAGE;
        const uint32_t kb_l = kb_h + KVMAT;
        const uint32_t vb_h = kb_h + 2 * KVMAT;
        const uint32_t vb_l = kb_h + 3 * KVMAT;

        // ---- S = Q K^T (2-product fp16) ----
        float sc[8][4];
#pragma unroll
        for (int j = 0; j < 8; j++)
#pragma unroll
            for (int r = 0; r < 4; r++) sc[j][r] = 0.0f;

#pragma unroll
        for (int ks = 0; ks < 4; ks++) {
            const int kk = ks * 16;
            uint32_t qa[4];
            LDSM_X4(qa[0], qa[1], qa[2], qa[3], sb + AQ + a_off + kk * 2);
#pragma unroll
            for (int j = 0; j < 8; j++) {
                const uint32_t ka = (uint32_t)(j * 8 * AP + kk) * 2 + k_off;
                uint32_t bh[2], bl[2];
                LDSM_X2(bh[0], bh[1], kb_h + ka);
                LDSM_X2(bl[0], bl[1], kb_l + ka);
                mma16816h(sc[j], qa, bh, sc[j]);
                mma16816h(sc[j], qa, bl, sc[j]);
            }
        }

        // ---- mask + online softmax ----
        float mx0 = -1e30f, mx1 = -1e30f;
#pragma unroll
        for (int j = 0; j < 8; j++) {
#pragma unroll
            for (int e = 0; e < 2; e++) {
                const int key = k0 + 8 * j + 2 * tig + e;
                float s0 = sc[j][e] * scale;     if (key > row0) s0 = 0.0f;
                float s1 = sc[j][2 + e] * scale; if (key > row1) s1 = 0.0f;
                sc[j][e] = s0; sc[j][2 + e] = s1;
                mx0 = fmaxf(mx0, s0); mx1 = fmaxf(mx1, s1);
            }
        }
        mx0 = fmaxf(mx0, __shfl_xor_sync(0xffffffffu, mx0, 1));
        mx0 = fmaxf(mx0, __shfl_xor_sync(0xffffffffu, mx0, 2));
        mx1 = fmaxf(mx1, __shfl_xor_sync(0xffffffffu, mx1, 1));
        mx1 = fmaxf(mx1, __shfl_xor_sync(0xffffffffu, mx1, 2));
        const float mn0 = fmaxf(m0, mx0), mn1 = fmaxf(m1, mx1);
        const float al0 = __expf(m0 - mn0), al1 = __expf(m1 - mn1);
        m0 = mn0; m1 = mn1;
        float ls0 = 0.0f, ls1 = 0.0f;
#pragma unroll
        for (int j = 0; j < 8; j++) {
#pragma unroll
            for (int e = 0; e < 2; e++) {
                float p0 = __expf(sc[j][e] - mn0);
                float p1 = __expf(sc[j][2 + e] - mn1);
                sc[j][e] = p0; sc[j][2 + e] = p1;
                ls0 += p0; ls1 += p1;
            }
        }
        l0 = l0 * al0 + ls0;
        l1 = l1 * al1 + ls1;
#pragma unroll
        for (int j = 0; j < 8; j++) {
            oc[j][0] *= al0; oc[j][1] *= al0;
            oc[j][2] *= al1; oc[j][3] *= al1;
        }

        // ---- PV: P16 unsplit, V hi/lo 2-product ----
#pragma unroll
        for (int t = 0; t < 4; t++) {
            const int kk = t * 16;
            uint32_t pa[4];
            {
                const float* cA = sc[2 * t];
                const float* cB = sc[2 * t + 1];
                pa[0] = packh2(cA[0], cA[1]);  pa[1] = packh2(cA[2], cA[3]);
                pa[2] = packh2(cB[0], cB[1]);  pa[3] = packh2(cB[2], cB[3]);
            }
#pragma unroll
            for (int j = 0; j < 8; j++) {
                const uint32_t va = (uint32_t)(kk * AP + j * 8) * 2 + v_off;
                uint32_t vh[2], vl[2];
                LDSM_X2_T(vh[0], vh[1], vb_h + va);
                LDSM_X2_T(vl[0], vl[1], vb_l + va);
                mma16816h(oc[j], pa, vh, oc[j]);
                mma16816h(oc[j], pa, vl, oc[j]);
            }
        }
    }

    l0 += __shfl_xor_sync(0xffffffffu, l0, 1);
    l0 += __shfl_xor_sync(0xffffffffu, l0, 2);
    l1 += __shfl_xor_sync(0xffffffffu, l1, 1);
    l1 += __shfl_xor_sync(0xffffffffu, l1, 2);

    const int cnt = S_ - 128 * (qt + 1);
    if (cnt > 0) {
        const float nn0 = fmaxf(m0, 0.0f), nn1 = fmaxf(m1, 0.0f);
        const float a20 = __expf(m0 - nn0), a21 = __expf(m1 - nn1);
        const float e00 = __expf(-nn0), e01 = __expf(-nn1);
        l0 = l0 * a20 + (float)cnt * e00;
        l1 = l1 * a21 + (float)cnt * e01;
        const float* sv = &sufv[((size_t)(b * H_ + h) * 33 + 2 * (qt + 1)) * 64];
#pragma unroll
        for (int j = 0; j < 8; j++) {
#pragma unroll
            for (int e = 0; e < 2; e++) {
                const float svv = sv[8 * j + 2 * tig + e];
                oc[j][e]     = oc[j][e]     * a20 + e00 * svv;
                oc[j][2 + e] = oc[j][2 + e] * a21 + e01 * svv;
            }
        }
    }
    const float inv0 = 1.0f / l0, inv1 = 1.0f / l1;

    const size_t ob0 = (size_t)(b * S_ + row0) * D_ + h * 64;
    const size_t ob1 = (size_t)(b * S_ + row1) * D_ + h * 64;
#pragma unroll
    for (int j = 0; j < 8; j++) {
        const int d0 = 8 * j + 2 * tig;
        *(uint32_t*)&att16[ob0 + d0] = packh2(oc[j][0] * inv0, oc[j][1] * inv0);
        *(uint32_t*)&att16[ob1 + d0] = packh2(oc[j][2] * inv1, oc[j][3] * inv1);
    }
}

// ---------------------------------------------------------------------------
__global__ void __launch_bounds__(256) ln_kernel(const float* __restrict__ x,
                                                 const float* __restrict__ y,
                                                 const float* __restrict__ gamma,
                                                 const float* __restrict__ beta,
                                                 float* __restrict__ out) {
    __shared__ float red[8];
    const int row = blockIdx.x, t = threadIdx.x;
    const int lane = t & 31, wid = t >> 5;
    const size_t off = (size_t)row * D_;

    float v[4], s = 0.0f;
#pragma unroll
    for (int i = 0; i < 4; i++) {
        int idx = t + i * 256;
        v[i] = x[off + idx] + y[off + idx];
        s += v[i];
    }
    for (int d = 16; d > 0; d >>= 1) s += __shfl_xor_sync(0xffffffffu, s, d);
    if (lane == 0) red[wid] = s;
    __syncthreads();
    float tot = 0.0f;
#pragma unroll
    for (int w = 0; w < 8; w++) tot += red[w];
    const float mean = tot * (1.0f / D_);
    __syncthreads();
    float ss = 0.0f;
#pragma unroll
    for (int i = 0; i < 4; i++) { float d = v[i] - mean; ss += d * d; }
    for (int d = 16; d > 0; d >>= 1) ss += __shfl_xor_sync(0xffffffffu, ss, d);
    if (lane == 0) red[wid] = ss;
    __syncthreads();
    float tot2 = 0.0f;
#pragma unroll
    for (int w = 0; w < 8; w++) tot2 += red[w];
    const float rstd = rsqrtf(tot2 * (1.0f / D_) + 1e-3f);
#pragma unroll
    for (int i = 0; i < 4; i++) {
        int idx = t + i * 256;
        out[off + idx] = (v[i] - mean) * rstd * gamma[idx] + beta[idx];
    }
}

// ---------------------------------------------------------------------------
extern "C" void kernel_launch(void* const* d_in, const int* in_sizes, int n_in,
                              void* d_out, int out_size) {
    const float* x       = (const float*)d_in[0];
    const float* W_embed = (const float*)d_in[2];
    const float* W_out   = (const float*)d_in[3];
    const float* gamma   = (const float*)d_in[4];
    const float* beta    = (const float*)d_in[5];
    float* out = (float*)d_out;

    __half *qhi, *qlo, *x16, *weh, *wel, *woh, *wol, *att16;
    float *y, *sufv;
    cudaGetSymbolAddress((void**)&qhi,   g_qkvhi);
    cudaGetSymbolAddress((void**)&qlo,   g_qkvlo);
    cudaGetSymbolAddress((void**)&x16,   g_x16);
    cudaGetSymbolAddress((void**)&weh,   g_weh16);
    cudaGetSymbolAddress((void**)&wel,   g_wel16);
    cudaGetSymbolAddress((void**)&woh,   g_woh16);
    cudaGetSymbolAddress((void**)&wol,   g_wol16);
    cudaGetSymbolAddress((void**)&att16, g_att16);
    cudaGetSymbolAddress((void**)&y,     g_y);
    cudaGetSymbolAddress((void**)&sufv,  g_sufv);

    cudaFuncSetAttribute(gemm_h<0>, cudaFuncAttributeMaxDynamicSharedMemorySize, GSMEM);
    cudaFuncSetAttribute(gemm_h<1>, cudaFuncAttributeMaxDynamicSharedMemorySize, GSMEM);
    cudaFuncSetAttribute(attn_mma, cudaFuncAttributeMaxDynamicSharedMemorySize, ASMEM);

    convert4<<<(MROWS * D_ / 4 + 255) / 256, 256>>>((const float4*)x, (__half2*)x16,
                                                    MROWS * D_ / 4);
    transpose_split16<<<dim3(NQKV / 32, D_ / 32), dim3(32, 8)>>>(W_embed, weh, wel, D_, NQKV);
    transpose_split16<<<dim3(D_ / 32, D_ / 32), dim3(32, 8)>>>(W_out, woh, wol, D_, D_);

    gemm_h<1><<<dim3(NQKV / BN, MROWS / BM), 256, GSMEM>>>(
        x16, weh, wel, nullptr, qhi, qlo, MROWS, NQKV, D_);

    sufv_partial<<<dim3(32, H_, B_), 64>>>(qhi, qlo, sufv);
    sufv_scan<<<dim3(H_, B_), 64>>>(sufv);

    attn_mma<<<dim3(S_ / 128, H_, B_), 256, ASMEM>>>(qhi, qlo, sufv, att16);

    gemm_h<0><<<dim3(D_ / BN, MROWS / BM), 256, GSMEM>>>(
        att16, woh, wol, y, nullptr, nullptr, MROWS, D_, D_);

    ln_kernel<<<MROWS, 256>>>(x, y, gamma, beta, out);
}